// round 8
// baseline (speedup 1.0000x reference)
#include <cuda_runtime.h>
#include <cuda_bf16.h>
#include <cuda_fp8.h>
#include <cstdint>
#include <math.h>

#define TOKENS 16384
#define HIDDEN 2048
#define NGROUP (HIDDEN / 128)
#define NKT (HIDDEN / 32)     // 64 k-tiles of BK=32

// ---------------- scratch (device globals; no allocation allowed) ----------------
__device__ __nv_bfloat16 g_wb[3][(size_t)HIDDEN * HIDDEN];   // bf16 weights [K,N]
__device__ __nv_bfloat16 g_act[(size_t)TOKENS * HIDDEN];     // bf16 activations (GEMM A)
__device__ float         g_resid[(size_t)TOKENS * HIDDEN];   // fp32 residual
__device__ float         g_gemm[(size_t)TOKENS * HIDDEN];    // fp32 GEMM output

// ---------------- helpers ----------------
__device__ __forceinline__ void cp_async16(uint32_t saddr, const void* gptr) {
    asm volatile("cp.async.cg.shared.global [%0], [%1], 16;\n" :: "r"(saddr), "l"(gptr));
}

__device__ __forceinline__ void ldsm_x4(uint32_t& r0, uint32_t& r1, uint32_t& r2, uint32_t& r3, uint32_t a) {
    asm volatile("ldmatrix.sync.aligned.m8n8.x4.shared.b16 {%0,%1,%2,%3}, [%4];\n"
                 : "=r"(r0), "=r"(r1), "=r"(r2), "=r"(r3) : "r"(a));
}
__device__ __forceinline__ void ldsm_x4t(uint32_t& r0, uint32_t& r1, uint32_t& r2, uint32_t& r3, uint32_t a) {
    asm volatile("ldmatrix.sync.aligned.m8n8.x4.trans.shared.b16 {%0,%1,%2,%3}, [%4];\n"
                 : "=r"(r0), "=r"(r1), "=r"(r2), "=r"(r3) : "r"(a));
}

__device__ __forceinline__ void mma16816(float* c, const uint32_t* a, const uint32_t* b) {
    asm volatile(
        "mma.sync.aligned.m16n8k16.row.col.f32.bf16.bf16.f32 "
        "{%0,%1,%2,%3}, {%4,%5,%6,%7}, {%8,%9}, {%0,%1,%2,%3};\n"
        : "+f"(c[0]), "+f"(c[1]), "+f"(c[2]), "+f"(c[3])
        : "r"(a[0]), "r"(a[1]), "r"(a[2]), "r"(a[3]), "r"(b[0]), "r"(b[1]));
}

__device__ __forceinline__ float block_sum_256(float v) {
    __shared__ float red[8];
    #pragma unroll
    for (int o = 16; o; o >>= 1) v += __shfl_xor_sync(0xffffffffu, v, o);
    if ((threadIdx.x & 31) == 0) red[threadIdx.x >> 5] = v;
    __syncthreads();
    float s = 0.f;
    #pragma unroll
    for (int i = 0; i < 8; i++) s += red[i];
    return s;
}

// ---------------- weight fp32 -> bf16 ----------------
__global__ __launch_bounds__(256) void k_convert_w(const float* __restrict__ w) {
    size_t total = (size_t)3 * HIDDEN * HIDDEN / 4;
    const float4* src = (const float4*)w;
    __nv_bfloat162* dst = (__nv_bfloat162*)&g_wb[0][0];
    for (size_t i = (size_t)blockIdx.x * blockDim.x + threadIdx.x; i < total;
         i += (size_t)gridDim.x * blockDim.x) {
        float4 v = src[i];
        dst[2 * i]     = __floats2bfloat162_rn(v.x, v.y);
        dst[2 * i + 1] = __floats2bfloat162_rn(v.z, v.w);
    }
}

// ---------------- stage 0: z = relu(x); resid = z; y = rmsnorm(z)*w0 -> bf16 ----------------
__global__ __launch_bounds__(256) void k_relu_rmsnorm(const float* __restrict__ x,
                                                      const float* __restrict__ nwr) {
    int row = blockIdx.x;
    int t = threadIdx.x;
    size_t base = (size_t)row * HIDDEN;
    const float4* xp = (const float4*)(x + base);
    float4 v0 = xp[2 * t], v1 = xp[2 * t + 1];
    float z[8];
    z[0] = fmaxf(v0.x, 0.f); z[1] = fmaxf(v0.y, 0.f); z[2] = fmaxf(v0.z, 0.f); z[3] = fmaxf(v0.w, 0.f);
    z[4] = fmaxf(v1.x, 0.f); z[5] = fmaxf(v1.y, 0.f); z[6] = fmaxf(v1.z, 0.f); z[7] = fmaxf(v1.w, 0.f);
    float ss = 0.f;
    #pragma unroll
    for (int i = 0; i < 8; i++) ss += z[i] * z[i];
    ss = block_sum_256(ss);
    float rinv = 1.0f / sqrtf(ss * (1.0f / HIDDEN) + 1e-5f);

    float4* rp = (float4*)(g_resid + base);
    rp[2 * t]     = make_float4(z[0], z[1], z[2], z[3]);
    rp[2 * t + 1] = make_float4(z[4], z[5], z[6], z[7]);

    const float4* wp = (const float4*)nwr;
    float4 w0 = wp[2 * t], w1 = wp[2 * t + 1];
    float wv[8] = {w0.x, w0.y, w0.z, w0.w, w1.x, w1.y, w1.z, w1.w};

    union { __nv_bfloat162 h2[4]; uint4 u; } yb;
    #pragma unroll
    for (int i = 0; i < 4; i++)
        yb.h2[i] = __floats2bfloat162_rn(z[2 * i] * rinv * wv[2 * i],
                                         z[2 * i + 1] * rinv * wv[2 * i + 1]);
    ((uint4*)(g_act + base))[t] = yb.u;
}

// ---------------- fused add + rmsnorm + group quant (ue8m0 / e4m3) ----------------
__global__ __launch_bounds__(256) void k_add_rmsnorm_quant(const float* __restrict__ nwr,
                                                           float* __restrict__ out_scale) {
    int row = blockIdx.x;
    int t = threadIdx.x;
    size_t base = (size_t)row * HIDDEN;
    const float4* gp = (const float4*)(g_gemm + base);
    float4* rp = (float4*)(g_resid + base);
    float4 a0 = gp[2 * t], a1 = gp[2 * t + 1];
    float4 r0 = rp[2 * t], r1 = rp[2 * t + 1];
    float z[8] = {a0.x + r0.x, a0.y + r0.y, a0.z + r0.z, a0.w + r0.w,
                  a1.x + r1.x, a1.y + r1.y, a1.z + r1.z, a1.w + r1.w};
    rp[2 * t]     = make_float4(z[0], z[1], z[2], z[3]);
    rp[2 * t + 1] = make_float4(z[4], z[5], z[6], z[7]);

    float ss = 0.f;
    #pragma unroll
    for (int i = 0; i < 8; i++) ss += z[i] * z[i];
    ss = block_sum_256(ss);
    float rinv = 1.0f / sqrtf(ss * (1.0f / HIDDEN) + 1e-5f);

    const float4* wp = (const float4*)nwr;
    float4 w0 = wp[2 * t], w1 = wp[2 * t + 1];
    float wv[8] = {w0.x, w0.y, w0.z, w0.w, w1.x, w1.y, w1.z, w1.w};

    float y[8];
    float am = 0.f;
    #pragma unroll
    for (int i = 0; i < 8; i++) {
        y[i] = z[i] * rinv * wv[i];
        am = fmaxf(am, fabsf(y[i]));
    }
    #pragma unroll
    for (int o = 8; o; o >>= 1) am = fmaxf(am, __shfl_xor_sync(0xffffffffu, am, o));

    float s0 = fmaxf(am, 1e-10f) / 448.0f;
    int e;
    float m = frexpf(s0, &e);
    if (m == 0.5f) e -= 1;
    float scale = ldexpf(1.0f, e);
    if ((t & 15) == 0) out_scale[(size_t)row * NGROUP + (t >> 4)] = scale;

    float inv = 1.0f / scale;
    union { __nv_bfloat162 h2[4]; uint4 u; } yb;
    #pragma unroll
    for (int i = 0; i < 4; i++) {
        __nv_fp8_e4m3 q0 = __nv_fp8_e4m3(y[2 * i] * inv);
        __nv_fp8_e4m3 q1 = __nv_fp8_e4m3(y[2 * i + 1] * inv);
        yb.h2[i] = __floats2bfloat162_rn((float)q0, (float)q1);
    }
    ((uint4*)(g_act + base))[t] = yb.u;
}

// ---------------- final: y4 = rmsnorm(x4 + resid)*w3 -> out fp32 ----------------
__global__ __launch_bounds__(256) void k_add_rmsnorm_out(const float* __restrict__ nwr,
                                                         float* __restrict__ out) {
    int row = blockIdx.x;
    int t = threadIdx.x;
    size_t base = (size_t)row * HIDDEN;
    const float4* gp = (const float4*)(g_gemm + base);
    const float4* rp = (const float4*)(g_resid + base);
    float4 a0 = gp[2 * t], a1 = gp[2 * t + 1];
    float4 r0 = rp[2 * t], r1 = rp[2 * t + 1];
    float z[8] = {a0.x + r0.x, a0.y + r0.y, a0.z + r0.z, a0.w + r0.w,
                  a1.x + r1.x, a1.y + r1.y, a1.z + r1.z, a1.w + r1.w};
    float ss = 0.f;
    #pragma unroll
    for (int i = 0; i < 8; i++) ss += z[i] * z[i];
    ss = block_sum_256(ss);
    float rinv = 1.0f / sqrtf(ss * (1.0f / HIDDEN) + 1e-5f);

    const float4* wp = (const float4*)nwr;
    float4 w0 = wp[2 * t], w1 = wp[2 * t + 1];
    float wv[8] = {w0.x, w0.y, w0.z, w0.w, w1.x, w1.y, w1.z, w1.w};

    float4* op = (float4*)(out + base);
    op[2 * t]     = make_float4(z[0] * rinv * wv[0], z[1] * rinv * wv[1],
                                z[2] * rinv * wv[2], z[3] * rinv * wv[3]);
    op[2 * t + 1] = make_float4(z[4] * rinv * wv[4], z[5] * rinv * wv[5],
                                z[6] * rinv * wv[6], z[7] * rinv * wv[7]);
}

// ---------------- GEMM: g_gemm[M,N] = g_act[M,K](bf16) x g_wb[widx][K,N](bf16), fp32 acc ----------------
// Block 256x128x32, 8 warps in 4(M) x 2(N), warp tile 64x64 (32 MMA per 8 ldmatrix).
// 4-stage cp.async pipeline, one __syncthreads per iteration, prefetch distance 3.
// Padded shared rows (A: 40 halves, B: 136 halves) -> conflict-free ldmatrix.
#define ASTR 40
#define BSTR 136
#define NSTAGE 4
#define SZA (256 * ASTR * 2)               // 20480 B per stage
#define SZB (32 * BSTR * 2)                // 8704 B per stage
#define GEMM_SMEM (NSTAGE * (SZA + SZB))   // 116736 bytes

__global__ __launch_bounds__(256, 1) void k_gemm(int widx) {
    extern __shared__ __align__(16) char smem[];

    const __nv_bfloat16* A = g_act;
    const __nv_bfloat16* B = g_wb[widx];
    float* C = g_gemm;

    int tid = threadIdx.x;
    int bn = blockIdx.x, bm = blockIdx.y;
    int lane = tid & 31, warp = tid >> 5;
    int wm = warp >> 1;  // 0..3 along M (64 rows each)
    int wn = warp & 1;   // 0..1 along N (64 cols each)

    // global->shared load mapping (16B per cp.async)
    int a_row = tid >> 2;            // 0..63 (4 groups of 64 rows)
    int a_col = (tid & 3) * 8;       // halves
    int b_row = tid >> 4;            // 0..15 (+16)
    int b_col = (tid & 15) * 8;      // halves

    const __nv_bfloat16* gA0 = A + (size_t)(bm * 256 + a_row) * HIDDEN + a_col;
    const __nv_bfloat16* gB0 = B + (size_t)b_row * HIDDEN + bn * 128 + b_col;
    const __nv_bfloat16* gB1 = gB0 + (size_t)16 * HIDDEN;

    uint32_t sA = (uint32_t)__cvta_generic_to_shared(smem);
    uint32_t sB = sA + NSTAGE * SZA;
    uint32_t sAw = sA + (a_row * ASTR + a_col) * 2;
    uint32_t sBw = sB + (b_row * BSTR + b_col) * 2;

#define LOADSTAGE(s, k0)                                                          \
    {                                                                             \
        cp_async16(sAw + (s) * SZA,                  gA0 + (k0));                 \
        cp_async16(sAw + (s) * SZA + 64 * ASTR * 2,  gA0 + (size_t)64 * HIDDEN + (k0)); \
        cp_async16(sAw + (s) * SZA + 128 * ASTR * 2, gA0 + (size_t)128 * HIDDEN + (k0)); \
        cp_async16(sAw + (s) * SZA + 192 * ASTR * 2, gA0 + (size_t)192 * HIDDEN + (k0)); \
        cp_async16(sBw + (s) * SZB,                  gB0 + (size_t)(k0) * HIDDEN); \
        cp_async16(sBw + (s) * SZB + 16 * BSTR * 2,  gB1 + (size_t)(k0) * HIDDEN); \
        asm volatile("cp.async.commit_group;\n" ::: "memory");                    \
    }

    // ldmatrix base addresses (bytes)
    uint32_t aAbase = sA + ((wm * 64 + (lane & 15)) * ASTR + (lane >> 4) * 8) * 2;
    uint32_t aBbase = sB + ((lane & 15) * BSTR + wn * 64 + (lane >> 4) * 8) * 2;

    float acc[4][8][4] = {};

    LOADSTAGE(0, 0);
    LOADSTAGE(1, 32);
    LOADSTAGE(2, 64);

    for (int kt = 0; kt < NKT; kt++) {
        int s = kt & (NSTAGE - 1);
        // stage kt complete once at most 2 newer groups are outstanding
        asm volatile("cp.async.wait_group 2;\n" ::: "memory");
        __syncthreads();   // also guarantees all warps finished reading stage kt-1

        int jn = kt + 3;
        if (jn < NKT) {
            LOADSTAGE(jn & (NSTAGE - 1), jn * 32);   // overwrites stage kt-1: safe post-barrier
        } else {
            asm volatile("cp.async.commit_group;\n" ::: "memory");  // uniform group accounting
        }

        #pragma unroll
        for (int kk = 0; kk < 32; kk += 16) {
            uint32_t af[4][4];
            uint32_t bf[8][2];
            #pragma unroll
            for (int mt = 0; mt < 4; mt++)
                ldsm_x4(af[mt][0], af[mt][1], af[mt][2], af[mt][3],
                        aAbase + s * SZA + (mt * 16 * ASTR + kk) * 2);
            #pragma unroll
            for (int np = 0; np < 4; np++) {
                uint32_t r0, r1, r2, r3;
                ldsm_x4t(r0, r1, r2, r3,
                         aBbase + s * SZB + (kk * BSTR + np * 16) * 2);
                bf[2 * np][0] = r0; bf[2 * np][1] = r1;
                bf[2 * np + 1][0] = r2; bf[2 * np + 1][1] = r3;
            }
            #pragma unroll
            for (int mt = 0; mt < 4; mt++)
                #pragma unroll
                for (int nt = 0; nt < 8; nt++)
                    mma16816(acc[mt][nt], af[mt], bf[nt]);
        }
    }

    // epilogue
    int gr = lane >> 2, gc = (lane & 3) * 2;
    #pragma unroll
    for (int mt = 0; mt < 4; mt++) {
        #pragma unroll
        for (int nt = 0; nt < 8; nt++) {
            int r = bm * 256 + wm * 64 + mt * 16 + gr;
            int c = bn * 128 + wn * 64 + nt * 8 + gc;
            *(float2*)&C[(size_t)r * HIDDEN + c] = make_float2(acc[mt][nt][0], acc[mt][nt][1]);
            *(float2*)&C[(size_t)(r + 8) * HIDDEN + c] = make_float2(acc[mt][nt][2], acc[mt][nt][3]);
        }
    }
#undef LOADSTAGE
}

// ---------------- launch ----------------
extern "C" void kernel_launch(void* const* d_in, const int* in_sizes, int n_in,
                              void* d_out, int out_size) {
    const float* x = (const float*)d_in[0];
    const float* nw = (const float*)d_in[1];
    const float* w = (const float*)d_in[2];
    float* out = (float*)d_out;
    float* y4 = out;
    float* y2s = out + (size_t)TOKENS * HIDDEN;
    float* y3s = y2s + (size_t)TOKENS * NGROUP;
    (void)in_sizes; (void)n_in; (void)out_size;

    static int configured = 0;
    if (!configured) {  // idempotent attribute set (host-side, graph-safe)
        cudaFuncSetAttribute(k_gemm, cudaFuncAttributeMaxDynamicSharedMemorySize, GEMM_SMEM);
        configured = 1;
    }

    dim3 gg(HIDDEN / 128, TOKENS / 256);   // (16, 64)

    k_convert_w<<<1184, 256>>>(w);
    k_relu_rmsnorm<<<TOKENS, 256>>>(x, nw);
    k_gemm<<<gg, 256, GEMM_SMEM>>>(0);
    k_add_rmsnorm_quant<<<TOKENS, 256>>>(nw + HIDDEN, y2s);
    k_gemm<<<gg, 256, GEMM_SMEM>>>(1);
    k_add_rmsnorm_quant<<<TOKENS, 256>>>(nw + 2 * HIDDEN, y3s);
    k_gemm<<<gg, 256, GEMM_SMEM>>>(2);
    k_add_rmsnorm_out<<<TOKENS, 256>>>(nw + 3 * HIDDEN, y4);
}

// round 10
// speedup vs baseline: 1.0665x; 1.0665x over previous
#include <cuda_runtime.h>
#include <cuda_bf16.h>
#include <cuda_fp8.h>
#include <cstdint>
#include <math.h>

#define TOKENS 16384
#define HIDDEN 2048
#define NGROUP (HIDDEN / 128)
#define NKT (HIDDEN / 64)     // 32 k-tiles of BK=64

// ---------------- scratch (device globals; no allocation allowed) ----------------
__device__ __nv_bfloat16 g_wb[3][(size_t)HIDDEN * HIDDEN];   // bf16 weights [K,N]
__device__ __nv_bfloat16 g_act[(size_t)TOKENS * HIDDEN];     // bf16 activations (GEMM A)
__device__ float         g_resid[(size_t)TOKENS * HIDDEN];   // fp32 residual
__device__ float         g_gemm[(size_t)TOKENS * HIDDEN];    // fp32 GEMM output

// ---------------- helpers ----------------
__device__ __forceinline__ void cp_async16(uint32_t saddr, const void* gptr) {
    asm volatile("cp.async.cg.shared.global [%0], [%1], 16;\n" :: "r"(saddr), "l"(gptr));
}

__device__ __forceinline__ void ldsm_x4(uint32_t& r0, uint32_t& r1, uint32_t& r2, uint32_t& r3, uint32_t a) {
    asm volatile("ldmatrix.sync.aligned.m8n8.x4.shared.b16 {%0,%1,%2,%3}, [%4];\n"
                 : "=r"(r0), "=r"(r1), "=r"(r2), "=r"(r3) : "r"(a));
}
__device__ __forceinline__ void ldsm_x4t(uint32_t& r0, uint32_t& r1, uint32_t& r2, uint32_t& r3, uint32_t a) {
    asm volatile("ldmatrix.sync.aligned.m8n8.x4.trans.shared.b16 {%0,%1,%2,%3}, [%4];\n"
                 : "=r"(r0), "=r"(r1), "=r"(r2), "=r"(r3) : "r"(a));
}

__device__ __forceinline__ void mma16816(float* c, const uint32_t* a, const uint32_t* b) {
    asm volatile(
        "mma.sync.aligned.m16n8k16.row.col.f32.bf16.bf16.f32 "
        "{%0,%1,%2,%3}, {%4,%5,%6,%7}, {%8,%9}, {%0,%1,%2,%3};\n"
        : "+f"(c[0]), "+f"(c[1]), "+f"(c[2]), "+f"(c[3])
        : "r"(a[0]), "r"(a[1]), "r"(a[2]), "r"(a[3]), "r"(b[0]), "r"(b[1]));
}

__device__ __forceinline__ float block_sum_256(float v) {
    __shared__ float red[8];
    #pragma unroll
    for (int o = 16; o; o >>= 1) v += __shfl_xor_sync(0xffffffffu, v, o);
    if ((threadIdx.x & 31) == 0) red[threadIdx.x >> 5] = v;
    __syncthreads();
    float s = 0.f;
    #pragma unroll
    for (int i = 0; i < 8; i++) s += red[i];
    return s;
}

// ---------------- weight fp32 -> bf16 ----------------
__global__ __launch_bounds__(256) void k_convert_w(const float* __restrict__ w) {
    size_t total = (size_t)3 * HIDDEN * HIDDEN / 4;
    const float4* src = (const float4*)w;
    __nv_bfloat162* dst = (__nv_bfloat162*)&g_wb[0][0];
    for (size_t i = (size_t)blockIdx.x * blockDim.x + threadIdx.x; i < total;
         i += (size_t)gridDim.x * blockDim.x) {
        float4 v = src[i];
        dst[2 * i]     = __floats2bfloat162_rn(v.x, v.y);
        dst[2 * i + 1] = __floats2bfloat162_rn(v.z, v.w);
    }
}

// ---------------- stage 0: z = relu(x); resid = z; y = rmsnorm(z)*w0 -> bf16 ----------------
__global__ __launch_bounds__(256) void k_relu_rmsnorm(const float* __restrict__ x,
                                                      const float* __restrict__ nwr) {
    int row = blockIdx.x;
    int t = threadIdx.x;
    size_t base = (size_t)row * HIDDEN;
    const float4* xp = (const float4*)(x + base);
    float4 v0 = xp[2 * t], v1 = xp[2 * t + 1];
    float z[8];
    z[0] = fmaxf(v0.x, 0.f); z[1] = fmaxf(v0.y, 0.f); z[2] = fmaxf(v0.z, 0.f); z[3] = fmaxf(v0.w, 0.f);
    z[4] = fmaxf(v1.x, 0.f); z[5] = fmaxf(v1.y, 0.f); z[6] = fmaxf(v1.z, 0.f); z[7] = fmaxf(v1.w, 0.f);
    float ss = 0.f;
    #pragma unroll
    for (int i = 0; i < 8; i++) ss += z[i] * z[i];
    ss = block_sum_256(ss);
    float rinv = 1.0f / sqrtf(ss * (1.0f / HIDDEN) + 1e-5f);

    float4* rp = (float4*)(g_resid + base);
    rp[2 * t]     = make_float4(z[0], z[1], z[2], z[3]);
    rp[2 * t + 1] = make_float4(z[4], z[5], z[6], z[7]);

    const float4* wp = (const float4*)nwr;
    float4 w0 = wp[2 * t], w1 = wp[2 * t + 1];
    float wv[8] = {w0.x, w0.y, w0.z, w0.w, w1.x, w1.y, w1.z, w1.w};

    union { __nv_bfloat162 h2[4]; uint4 u; } yb;
    #pragma unroll
    for (int i = 0; i < 4; i++)
        yb.h2[i] = __floats2bfloat162_rn(z[2 * i] * rinv * wv[2 * i],
                                         z[2 * i + 1] * rinv * wv[2 * i + 1]);
    ((uint4*)(g_act + base))[t] = yb.u;
}

// ---------------- fused add + rmsnorm + group quant (ue8m0 / e4m3) ----------------
__global__ __launch_bounds__(256) void k_add_rmsnorm_quant(const float* __restrict__ nwr,
                                                           float* __restrict__ out_scale) {
    int row = blockIdx.x;
    int t = threadIdx.x;
    size_t base = (size_t)row * HIDDEN;
    const float4* gp = (const float4*)(g_gemm + base);
    float4* rp = (float4*)(g_resid + base);
    float4 a0 = gp[2 * t], a1 = gp[2 * t + 1];
    float4 r0 = rp[2 * t], r1 = rp[2 * t + 1];
    float z[8] = {a0.x + r0.x, a0.y + r0.y, a0.z + r0.z, a0.w + r0.w,
                  a1.x + r1.x, a1.y + r1.y, a1.z + r1.z, a1.w + r1.w};
    rp[2 * t]     = make_float4(z[0], z[1], z[2], z[3]);
    rp[2 * t + 1] = make_float4(z[4], z[5], z[6], z[7]);

    float ss = 0.f;
    #pragma unroll
    for (int i = 0; i < 8; i++) ss += z[i] * z[i];
    ss = block_sum_256(ss);
    float rinv = 1.0f / sqrtf(ss * (1.0f / HIDDEN) + 1e-5f);

    const float4* wp = (const float4*)nwr;
    float4 w0 = wp[2 * t], w1 = wp[2 * t + 1];
    float wv[8] = {w0.x, w0.y, w0.z, w0.w, w1.x, w1.y, w1.z, w1.w};

    float y[8];
    float am = 0.f;
    #pragma unroll
    for (int i = 0; i < 8; i++) {
        y[i] = z[i] * rinv * wv[i];
        am = fmaxf(am, fabsf(y[i]));
    }
    #pragma unroll
    for (int o = 8; o; o >>= 1) am = fmaxf(am, __shfl_xor_sync(0xffffffffu, am, o));

    float s0 = fmaxf(am, 1e-10f) / 448.0f;
    int e;
    float m = frexpf(s0, &e);
    if (m == 0.5f) e -= 1;
    float scale = ldexpf(1.0f, e);
    if ((t & 15) == 0) out_scale[(size_t)row * NGROUP + (t >> 4)] = scale;

    float inv = 1.0f / scale;
    union { __nv_bfloat162 h2[4]; uint4 u; } yb;
    #pragma unroll
    for (int i = 0; i < 4; i++) {
        __nv_fp8_e4m3 q0 = __nv_fp8_e4m3(y[2 * i] * inv);
        __nv_fp8_e4m3 q1 = __nv_fp8_e4m3(y[2 * i + 1] * inv);
        yb.h2[i] = __floats2bfloat162_rn((float)q0, (float)q1);
    }
    ((uint4*)(g_act + base))[t] = yb.u;
}

// ---------------- final: y4 = rmsnorm(x4 + resid)*w3 -> out fp32 ----------------
__global__ __launch_bounds__(256) void k_add_rmsnorm_out(const float* __restrict__ nwr,
                                                         float* __restrict__ out) {
    int row = blockIdx.x;
    int t = threadIdx.x;
    size_t base = (size_t)row * HIDDEN;
    const float4* gp = (const float4*)(g_gemm + base);
    const float4* rp = (const float4*)(g_resid + base);
    float4 a0 = gp[2 * t], a1 = gp[2 * t + 1];
    float4 r0 = rp[2 * t], r1 = rp[2 * t + 1];
    float z[8] = {a0.x + r0.x, a0.y + r0.y, a0.z + r0.z, a0.w + r0.w,
                  a1.x + r1.x, a1.y + r1.y, a1.z + r1.z, a1.w + r1.w};
    float ss = 0.f;
    #pragma unroll
    for (int i = 0; i < 8; i++) ss += z[i] * z[i];
    ss = block_sum_256(ss);
    float rinv = 1.0f / sqrtf(ss * (1.0f / HIDDEN) + 1e-5f);

    const float4* wp = (const float4*)nwr;
    float4 w0 = wp[2 * t], w1 = wp[2 * t + 1];
    float wv[8] = {w0.x, w0.y, w0.z, w0.w, w1.x, w1.y, w1.z, w1.w};

    float4* op = (float4*)(out + base);
    op[2 * t]     = make_float4(z[0] * rinv * wv[0], z[1] * rinv * wv[1],
                                z[2] * rinv * wv[2], z[3] * rinv * wv[3]);
    op[2 * t + 1] = make_float4(z[4] * rinv * wv[4], z[5] * rinv * wv[5],
                                z[6] * rinv * wv[6], z[7] * rinv * wv[7]);
}

// ---------------- GEMM: g_gemm[M,N] = g_act[M,K](bf16) x g_wb[widx][K,N](bf16), fp32 acc ----------------
// Block 128x128x64, 8 warps, warp tile 32x64 (R6 geometry, 2 CTAs/SM).
// 3-stage cp.async pipeline, BK=64 -> 32 barriers (half of R6), prefetch distance 2.
// Padded shared rows (A: 72 halves = 144B, B: 136 halves = 272B) -> conflict-free ldmatrix.
#define ASTR 72
#define BSTR 136
#define NSTAGE 3
#define SZA (128 * ASTR * 2)               // 18432 B per stage
#define SZB (64 * BSTR * 2)                // 17408 B per stage
#define GEMM_SMEM (NSTAGE * (SZA + SZB))   // 107520 bytes

__global__ __launch_bounds__(256, 2) void k_gemm(int widx) {
    extern __shared__ __align__(16) char smem[];

    const __nv_bfloat16* A = g_act;
    const __nv_bfloat16* B = g_wb[widx];
    float* C = g_gemm;

    int tid = threadIdx.x;
    int bn = blockIdx.x, bm = blockIdx.y;
    int lane = tid & 31, warp = tid >> 5;
    int wm = warp & 3;   // 0..3 along M (32 rows each)
    int wn = warp >> 2;  // 0..1 along N (64 cols each)

    // global->shared load mapping (16B per cp.async), 4 chunks A + 4 chunks B per thread
    int a_row = tid >> 3;            // 0..31 (4 groups of 32 rows)
    int a_col = (tid & 7) * 8;       // halves within 64-wide K row
    int b_row = tid >> 2;            // 0..63 (K rows)
    int b_col = (tid & 3) * 8;       // halves, 4 groups of 32

    const __nv_bfloat16* gA0 = A + (size_t)(bm * 128 + a_row) * HIDDEN + a_col;
    const __nv_bfloat16* gB0 = B + (size_t)b_row * HIDDEN + bn * 128 + b_col;

    uint32_t sA = (uint32_t)__cvta_generic_to_shared(smem);
    uint32_t sB = sA + NSTAGE * SZA;
    uint32_t sAw = sA + (a_row * ASTR + a_col) * 2;
    uint32_t sBw = sB + (b_row * BSTR + b_col) * 2;

#define LOADSTAGE(s, k0)                                                            \
    {                                                                               \
        cp_async16(sAw + (s) * SZA,                 gA0 + (k0));                    \
        cp_async16(sAw + (s) * SZA + 32 * ASTR * 2, gA0 + (size_t)32 * HIDDEN + (k0)); \
        cp_async16(sAw + (s) * SZA + 64 * ASTR * 2, gA0 + (size_t)64 * HIDDEN + (k0)); \
        cp_async16(sAw + (s) * SZA + 96 * ASTR * 2, gA0 + (size_t)96 * HIDDEN + (k0)); \
        cp_async16(sBw + (s) * SZB,            gB0 + (size_t)(k0) * HIDDEN);        \
        cp_async16(sBw + (s) * SZB + 32 * 2,   gB0 + (size_t)(k0) * HIDDEN + 32);   \
        cp_async16(sBw + (s) * SZB + 64 * 2,   gB0 + (size_t)(k0) * HIDDEN + 64);   \
        cp_async16(sBw + (s) * SZB + 96 * 2,   gB0 + (size_t)(k0) * HIDDEN + 96);   \
        asm volatile("cp.async.commit_group;\n" ::: "memory");                      \
    }

    // ldmatrix base addresses (bytes)
    uint32_t aAbase = sA + ((wm * 32 + (lane & 15)) * ASTR + (lane >> 4) * 8) * 2;
    uint32_t aBbase = sB + ((lane & 15) * BSTR + wn * 64 + (lane >> 4) * 8) * 2;

    float acc[2][8][4] = {};

    LOADSTAGE(0, 0);
    LOADSTAGE(1, 64);

    for (int kt = 0; kt < NKT; kt++) {
        int s = kt % NSTAGE;
        // stage kt complete once at most 1 newer group is outstanding
        asm volatile("cp.async.wait_group 1;\n" ::: "memory");
        __syncthreads();   // all warps finished reading stage kt-1

        int jn = kt + 2;
        if (jn < NKT) {
            LOADSTAGE(jn % NSTAGE, jn * 64);   // overwrites stage kt-1: safe post-barrier
        } else {
            asm volatile("cp.async.commit_group;\n" ::: "memory");  // uniform group accounting
        }

        #pragma unroll
        for (int kk = 0; kk < 64; kk += 16) {
            uint32_t af[2][4];
            uint32_t bf[8][2];
            #pragma unroll
            for (int mt = 0; mt < 2; mt++)
                ldsm_x4(af[mt][0], af[mt][1], af[mt][2], af[mt][3],
                        aAbase + s * SZA + (mt * 16 * ASTR + kk) * 2);
            #pragma unroll
            for (int np = 0; np < 4; np++) {
                uint32_t r0, r1, r2, r3;
                ldsm_x4t(r0, r1, r2, r3,
                         aBbase + s * SZB + (kk * BSTR + np * 16) * 2);
                bf[2 * np][0] = r0; bf[2 * np][1] = r1;
                bf[2 * np + 1][0] = r2; bf[2 * np + 1][1] = r3;
            }
            #pragma unroll
            for (int mt = 0; mt < 2; mt++)
                #pragma unroll
                for (int nt = 0; nt < 8; nt++)
                    mma16816(acc[mt][nt], af[mt], bf[nt]);
        }
    }

    // epilogue
    int gr = lane >> 2, gc = (lane & 3) * 2;
    #pragma unroll
    for (int mt = 0; mt < 2; mt++) {
        #pragma unroll
        for (int nt = 0; nt < 8; nt++) {
            int r = bm * 128 + wm * 32 + mt * 16 + gr;
            int c = bn * 128 + wn * 64 + nt * 8 + gc;
            *(float2*)&C[(size_t)r * HIDDEN + c] = make_float2(acc[mt][nt][0], acc[mt][nt][1]);
            *(float2*)&C[(size_t)(r + 8) * HIDDEN + c] = make_float2(acc[mt][nt][2], acc[mt][nt][3]);
        }
    }
#undef LOADSTAGE
}

// ---------------- launch ----------------
extern "C" void kernel_launch(void* const* d_in, const int* in_sizes, int n_in,
                              void* d_out, int out_size) {
    const float* x = (const float*)d_in[0];
    const float* nw = (const float*)d_in[1];
    const float* w = (const float*)d_in[2];
    float* out = (float*)d_out;
    float* y4 = out;
    float* y2s = out + (size_t)TOKENS * HIDDEN;
    float* y3s = y2s + (size_t)TOKENS * NGROUP;
    (void)in_sizes; (void)n_in; (void)out_size;

    static int configured = 0;
    if (!configured) {  // idempotent attribute set (host-side, graph-safe)
        cudaFuncSetAttribute(k_gemm, cudaFuncAttributeMaxDynamicSharedMemorySize, GEMM_SMEM);
        configured = 1;
    }

    dim3 gg(HIDDEN / 128, TOKENS / 128);   // (16, 128)

    k_convert_w<<<1184, 256>>>(w);
    k_relu_rmsnorm<<<TOKENS, 256>>>(x, nw);
    k_gemm<<<gg, 256, GEMM_SMEM>>>(0);
    k_add_rmsnorm_quant<<<TOKENS, 256>>>(nw + HIDDEN, y2s);
    k_gemm<<<gg, 256, GEMM_SMEM>>>(1);
    k_add_rmsnorm_quant<<<TOKENS, 256>>>(nw + 2 * HIDDEN, y3s);
    k_gemm<<<gg, 256, GEMM_SMEM>>>(2);
    k_add_rmsnorm_out<<<TOKENS, 256>>>(nw + 3 * HIDDEN, y4);
}

// round 11
// speedup vs baseline: 1.0918x; 1.0237x over previous
#include <cuda_runtime.h>
#include <cuda_bf16.h>
#include <cuda_fp8.h>
#include <cstdint>
#include <math.h>

#define TOKENS 16384
#define HIDDEN 2048
#define NGROUP (HIDDEN / 128)
#define NKT (HIDDEN / 32)     // 64 k-tiles of BK=32

// ---------------- scratch (device globals; no allocation allowed) ----------------
__device__ __nv_bfloat16 g_wb[3][(size_t)HIDDEN * HIDDEN];   // bf16 weights [K,N]
__device__ __nv_bfloat16 g_act[(size_t)TOKENS * HIDDEN];     // bf16 activations (GEMM A)
__device__ float         g_resid[(size_t)TOKENS * HIDDEN];   // fp32 residual (GEMM accumulates into it)

// ---------------- helpers ----------------
__device__ __forceinline__ void cp_async16(uint32_t saddr, const void* gptr) {
    asm volatile("cp.async.cg.shared.global [%0], [%1], 16;\n" :: "r"(saddr), "l"(gptr));
}

__device__ __forceinline__ void ldsm_x4(uint32_t& r0, uint32_t& r1, uint32_t& r2, uint32_t& r3, uint32_t a) {
    asm volatile("ldmatrix.sync.aligned.m8n8.x4.shared.b16 {%0,%1,%2,%3}, [%4];\n"
                 : "=r"(r0), "=r"(r1), "=r"(r2), "=r"(r3) : "r"(a));
}
__device__ __forceinline__ void ldsm_x4t(uint32_t& r0, uint32_t& r1, uint32_t& r2, uint32_t& r3, uint32_t a) {
    asm volatile("ldmatrix.sync.aligned.m8n8.x4.trans.shared.b16 {%0,%1,%2,%3}, [%4];\n"
                 : "=r"(r0), "=r"(r1), "=r"(r2), "=r"(r3) : "r"(a));
}

__device__ __forceinline__ void mma16816(float* c, const uint32_t* a, const uint32_t* b) {
    asm volatile(
        "mma.sync.aligned.m16n8k16.row.col.f32.bf16.bf16.f32 "
        "{%0,%1,%2,%3}, {%4,%5,%6,%7}, {%8,%9}, {%0,%1,%2,%3};\n"
        : "+f"(c[0]), "+f"(c[1]), "+f"(c[2]), "+f"(c[3])
        : "r"(a[0]), "r"(a[1]), "r"(a[2]), "r"(a[3]), "r"(b[0]), "r"(b[1]));
}

__device__ __forceinline__ float block_sum_256(float v) {
    __shared__ float red[8];
    #pragma unroll
    for (int o = 16; o; o >>= 1) v += __shfl_xor_sync(0xffffffffu, v, o);
    if ((threadIdx.x & 31) == 0) red[threadIdx.x >> 5] = v;
    __syncthreads();
    float s = 0.f;
    #pragma unroll
    for (int i = 0; i < 8; i++) s += red[i];
    return s;
}

// ---------------- weight fp32 -> bf16 ----------------
__global__ __launch_bounds__(256) void k_convert_w(const float* __restrict__ w) {
    size_t total = (size_t)3 * HIDDEN * HIDDEN / 4;
    const float4* src = (const float4*)w;
    __nv_bfloat162* dst = (__nv_bfloat162*)&g_wb[0][0];
    for (size_t i = (size_t)blockIdx.x * blockDim.x + threadIdx.x; i < total;
         i += (size_t)gridDim.x * blockDim.x) {
        float4 v = src[i];
        dst[2 * i]     = __floats2bfloat162_rn(v.x, v.y);
        dst[2 * i + 1] = __floats2bfloat162_rn(v.z, v.w);
    }
}

// ---------------- stage 0: z = relu(x); resid = z; y = rmsnorm(z)*w0 -> bf16 ----------------
__global__ __launch_bounds__(256) void k_relu_rmsnorm(const float* __restrict__ x,
                                                      const float* __restrict__ nwr) {
    int row = blockIdx.x;
    int t = threadIdx.x;
    size_t base = (size_t)row * HIDDEN;
    const float4* xp = (const float4*)(x + base);
    float4 v0 = xp[2 * t], v1 = xp[2 * t + 1];
    float z[8];
    z[0] = fmaxf(v0.x, 0.f); z[1] = fmaxf(v0.y, 0.f); z[2] = fmaxf(v0.z, 0.f); z[3] = fmaxf(v0.w, 0.f);
    z[4] = fmaxf(v1.x, 0.f); z[5] = fmaxf(v1.y, 0.f); z[6] = fmaxf(v1.z, 0.f); z[7] = fmaxf(v1.w, 0.f);
    float ss = 0.f;
    #pragma unroll
    for (int i = 0; i < 8; i++) ss += z[i] * z[i];
    ss = block_sum_256(ss);
    float rinv = 1.0f / sqrtf(ss * (1.0f / HIDDEN) + 1e-5f);

    float4* rp = (float4*)(g_resid + base);
    rp[2 * t]     = make_float4(z[0], z[1], z[2], z[3]);
    rp[2 * t + 1] = make_float4(z[4], z[5], z[6], z[7]);

    const float4* wp = (const float4*)nwr;
    float4 w0 = wp[2 * t], w1 = wp[2 * t + 1];
    float wv[8] = {w0.x, w0.y, w0.z, w0.w, w1.x, w1.y, w1.z, w1.w};

    union { __nv_bfloat162 h2[4]; uint4 u; } yb;
    #pragma unroll
    for (int i = 0; i < 4; i++)
        yb.h2[i] = __floats2bfloat162_rn(z[2 * i] * rinv * wv[2 * i],
                                         z[2 * i + 1] * rinv * wv[2 * i + 1]);
    ((uint4*)(g_act + base))[t] = yb.u;
}

// ---------------- rmsnorm + group quant (resid already updated by GEMM epilogue) ----------------
__global__ __launch_bounds__(256) void k_rmsnorm_quant(const float* __restrict__ nwr,
                                                       float* __restrict__ out_scale) {
    int row = blockIdx.x;
    int t = threadIdx.x;
    size_t base = (size_t)row * HIDDEN;
    const float4* rp = (const float4*)(g_resid + base);
    float4 r0 = rp[2 * t], r1 = rp[2 * t + 1];
    float z[8] = {r0.x, r0.y, r0.z, r0.w, r1.x, r1.y, r1.z, r1.w};

    float ss = 0.f;
    #pragma unroll
    for (int i = 0; i < 8; i++) ss += z[i] * z[i];
    ss = block_sum_256(ss);
    float rinv = 1.0f / sqrtf(ss * (1.0f / HIDDEN) + 1e-5f);

    const float4* wp = (const float4*)nwr;
    float4 w0 = wp[2 * t], w1 = wp[2 * t + 1];
    float wv[8] = {w0.x, w0.y, w0.z, w0.w, w1.x, w1.y, w1.z, w1.w};

    float y[8];
    float am = 0.f;
    #pragma unroll
    for (int i = 0; i < 8; i++) {
        y[i] = z[i] * rinv * wv[i];
        am = fmaxf(am, fabsf(y[i]));
    }
    // group = 128 elems = 16 consecutive threads
    #pragma unroll
    for (int o = 8; o; o >>= 1) am = fmaxf(am, __shfl_xor_sync(0xffffffffu, am, o));

    float s0 = fmaxf(am, 1e-10f) / 448.0f;
    int e;
    float m = frexpf(s0, &e);
    if (m == 0.5f) e -= 1;
    float scale = ldexpf(1.0f, e);
    if ((t & 15) == 0) out_scale[(size_t)row * NGROUP + (t >> 4)] = scale;

    float inv = 1.0f / scale;
    union { __nv_bfloat162 h2[4]; uint4 u; } yb;
    #pragma unroll
    for (int i = 0; i < 4; i++) {
        __nv_fp8_e4m3 q0 = __nv_fp8_e4m3(y[2 * i] * inv);
        __nv_fp8_e4m3 q1 = __nv_fp8_e4m3(y[2 * i + 1] * inv);
        yb.h2[i] = __floats2bfloat162_rn((float)q0, (float)q1);
    }
    ((uint4*)(g_act + base))[t] = yb.u;
}

// ---------------- final: y4 = rmsnorm(resid)*w3 -> out fp32 (resid updated by GEMM3) ----------------
__global__ __launch_bounds__(256) void k_rmsnorm_out(const float* __restrict__ nwr,
                                                     float* __restrict__ out) {
    int row = blockIdx.x;
    int t = threadIdx.x;
    size_t base = (size_t)row * HIDDEN;
    const float4* rp = (const float4*)(g_resid + base);
    float4 r0 = rp[2 * t], r1 = rp[2 * t + 1];
    float z[8] = {r0.x, r0.y, r0.z, r0.w, r1.x, r1.y, r1.z, r1.w};
    float ss = 0.f;
    #pragma unroll
    for (int i = 0; i < 8; i++) ss += z[i] * z[i];
    ss = block_sum_256(ss);
    float rinv = 1.0f / sqrtf(ss * (1.0f / HIDDEN) + 1e-5f);

    const float4* wp = (const float4*)nwr;
    float4 w0 = wp[2 * t], w1 = wp[2 * t + 1];
    float wv[8] = {w0.x, w0.y, w0.z, w0.w, w1.x, w1.y, w1.z, w1.w};

    float4* op = (float4*)(out + base);
    op[2 * t]     = make_float4(z[0] * rinv * wv[0], z[1] * rinv * wv[1],
                                z[2] * rinv * wv[2], z[3] * rinv * wv[3]);
    op[2 * t + 1] = make_float4(z[4] * rinv * wv[4], z[5] * rinv * wv[5],
                                z[6] * rinv * wv[6], z[7] * rinv * wv[7]);
}

// ---------------- GEMM: g_resid[M,N] += g_act[M,K](bf16) x g_wb[widx][K,N](bf16) ----------------
// Block 128x128x32, 8 warps, warp tile 32x64, 2 CTAs/SM (R6 proven geometry).
// 5-stage cp.async pipeline, prefetch distance 4, one __syncthreads per iteration.
// Epilogue fuses the residual add: resid = acc + resid (in place).
#define ASTR 40
#define BSTR 136
#define NSTAGE 5
#define SZA (128 * ASTR * 2)
#define SZB (32 * BSTR * 2)
#define GEMM_SMEM (NSTAGE * (SZA + SZB))   // 94720 bytes

__global__ __launch_bounds__(256, 2) void k_gemm(int widx) {
    extern __shared__ __align__(16) char smem[];

    const __nv_bfloat16* A = g_act;
    const __nv_bfloat16* B = g_wb[widx];
    float* R = g_resid;

    int tid = threadIdx.x;
    int bn = blockIdx.x, bm = blockIdx.y;
    int lane = tid & 31, warp = tid >> 5;
    int wm = warp & 3;   // 0..3 along M (32 rows each)
    int wn = warp >> 2;  // 0..1 along N (64 cols each)

    // global->shared load mapping (16B per cp.async)
    int a_row = tid >> 2;            // 0..63 (+64)
    int a_col = (tid & 3) * 8;       // halves
    int b_row = tid >> 4;            // 0..15 (+16)
    int b_col = (tid & 15) * 8;      // halves

    const __nv_bfloat16* gA0 = A + (size_t)(bm * 128 + a_row) * HIDDEN + a_col;
    const __nv_bfloat16* gA1 = gA0 + (size_t)64 * HIDDEN;
    const __nv_bfloat16* gB0 = B + (size_t)b_row * HIDDEN + bn * 128 + b_col;
    const __nv_bfloat16* gB1 = gB0 + (size_t)16 * HIDDEN;

    uint32_t sA = (uint32_t)__cvta_generic_to_shared(smem);
    uint32_t sB = sA + NSTAGE * SZA;
    uint32_t sAw = sA + (a_row * ASTR + a_col) * 2;
    uint32_t sBw = sB + (b_row * BSTR + b_col) * 2;

#define LOADSTAGE(s, k0)                                                        \
    {                                                                           \
        cp_async16(sAw + (s) * SZA, gA0 + (k0));                                \
        cp_async16(sAw + (s) * SZA + 64 * ASTR * 2, gA1 + (k0));                \
        cp_async16(sBw + (s) * SZB, gB0 + (size_t)(k0) * HIDDEN);               \
        cp_async16(sBw + (s) * SZB + 16 * BSTR * 2, gB1 + (size_t)(k0) * HIDDEN);\
        asm volatile("cp.async.commit_group;\n" ::: "memory");                  \
    }

    // ldmatrix base addresses (bytes)
    uint32_t aAbase = sA + ((wm * 32 + (lane & 15)) * ASTR + (lane >> 4) * 8) * 2;
    uint32_t aBbase = sB + ((lane & 15) * BSTR + wn * 64 + (lane >> 4) * 8) * 2;

    float acc[2][8][4] = {};

    LOADSTAGE(0, 0);
    LOADSTAGE(1, 32);
    LOADSTAGE(2, 64);
    LOADSTAGE(3, 96);

    for (int kt = 0; kt < NKT; kt++) {
        int s = kt % NSTAGE;
        // stage kt complete once at most 3 newer groups are outstanding
        asm volatile("cp.async.wait_group 3;\n" ::: "memory");
        __syncthreads();   // all warps finished reading stage kt-1

        int jn = kt + 4;
        if (jn < NKT) {
            LOADSTAGE(jn % NSTAGE, jn * 32);   // overwrites stage kt-1: safe post-barrier
        } else {
            asm volatile("cp.async.commit_group;\n" ::: "memory");  // uniform group accounting
        }

        #pragma unroll
        for (int kk = 0; kk < 32; kk += 16) {
            uint32_t af[2][4];
            uint32_t bf[8][2];
            #pragma unroll
            for (int mt = 0; mt < 2; mt++)
                ldsm_x4(af[mt][0], af[mt][1], af[mt][2], af[mt][3],
                        aAbase + s * SZA + (mt * 16 * ASTR + kk) * 2);
            #pragma unroll
            for (int np = 0; np < 4; np++) {
                uint32_t r0, r1, r2, r3;
                ldsm_x4t(r0, r1, r2, r3,
                         aBbase + s * SZB + (kk * BSTR + np * 16) * 2);
                bf[2 * np][0] = r0; bf[2 * np][1] = r1;
                bf[2 * np + 1][0] = r2; bf[2 * np + 1][1] = r3;
            }
            #pragma unroll
            for (int mt = 0; mt < 2; mt++)
                #pragma unroll
                for (int nt = 0; nt < 8; nt++)
                    mma16816(acc[mt][nt], af[mt], bf[nt]);
        }
    }

    // epilogue: fused residual add, in place (each element owned by one thread)
    int gr = lane >> 2, gc = (lane & 3) * 2;
    #pragma unroll
    for (int mt = 0; mt < 2; mt++) {
        #pragma unroll
        for (int nt = 0; nt < 8; nt++) {
            int r = bm * 128 + wm * 32 + mt * 16 + gr;
            int c = bn * 128 + wn * 64 + nt * 8 + gc;
            float2* p0 = (float2*)&R[(size_t)r * HIDDEN + c];
            float2* p1 = (float2*)&R[(size_t)(r + 8) * HIDDEN + c];
            float2 v0 = *p0, v1 = *p1;
            *p0 = make_float2(acc[mt][nt][0] + v0.x, acc[mt][nt][1] + v0.y);
            *p1 = make_float2(acc[mt][nt][2] + v1.x, acc[mt][nt][3] + v1.y);
        }
    }
#undef LOADSTAGE
}

// ---------------- launch ----------------
extern "C" void kernel_launch(void* const* d_in, const int* in_sizes, int n_in,
                              void* d_out, int out_size) {
    const float* x = (const float*)d_in[0];
    const float* nw = (const float*)d_in[1];
    const float* w = (const float*)d_in[2];
    float* out = (float*)d_out;
    float* y4 = out;
    float* y2s = out + (size_t)TOKENS * HIDDEN;
    float* y3s = y2s + (size_t)TOKENS * NGROUP;
    (void)in_sizes; (void)n_in; (void)out_size;

    static int configured = 0;
    if (!configured) {  // idempotent attribute set (host-side, graph-safe)
        cudaFuncSetAttribute(k_gemm, cudaFuncAttributeMaxDynamicSharedMemorySize, GEMM_SMEM);
        configured = 1;
    }

    dim3 gg(HIDDEN / 128, TOKENS / 128);

    k_convert_w<<<1184, 256>>>(w);
    k_relu_rmsnorm<<<TOKENS, 256>>>(x, nw);
    k_gemm<<<gg, 256, GEMM_SMEM>>>(0);          // resid += y @ w0
    k_rmsnorm_quant<<<TOKENS, 256>>>(nw + HIDDEN, y2s);
    k_gemm<<<gg, 256, GEMM_SMEM>>>(1);          // resid += y2q @ w1
    k_rmsnorm_quant<<<TOKENS, 256>>>(nw + 2 * HIDDEN, y3s);
    k_gemm<<<gg, 256, GEMM_SMEM>>>(2);          // resid += y3q @ w2
    k_rmsnorm_out<<<TOKENS, 256>>>(nw + 3 * HIDDEN, y4);
}

// round 12
// speedup vs baseline: 1.1101x; 1.0168x over previous
#include <cuda_runtime.h>
#include <cuda_bf16.h>
#include <cuda_fp8.h>
#include <cstdint>
#include <math.h>

#define TOKENS 16384
#define HIDDEN 2048
#define NGROUP (HIDDEN / 128)
#define NKT (HIDDEN / 32)     // 64 k-tiles of BK=32

// ---------------- scratch (device globals; no allocation allowed) ----------------
__device__ __nv_bfloat16 g_wb[3][(size_t)HIDDEN * HIDDEN];   // bf16 weights [K,N]
__device__ __nv_bfloat16 g_act[(size_t)TOKENS * HIDDEN];     // bf16 activations (GEMM A)
__device__ float         g_resid[(size_t)TOKENS * HIDDEN];   // fp32 residual (GEMM accumulates into it)

// ---------------- helpers ----------------
__device__ __forceinline__ void cp_async16(uint32_t saddr, const void* gptr) {
    asm volatile("cp.async.cg.shared.global [%0], [%1], 16;\n" :: "r"(saddr), "l"(gptr));
}

__device__ __forceinline__ void ldsm_x4(uint32_t& r0, uint32_t& r1, uint32_t& r2, uint32_t& r3, uint32_t a) {
    asm volatile("ldmatrix.sync.aligned.m8n8.x4.shared.b16 {%0,%1,%2,%3}, [%4];\n"
                 : "=r"(r0), "=r"(r1), "=r"(r2), "=r"(r3) : "r"(a));
}
__device__ __forceinline__ void ldsm_x4t(uint32_t& r0, uint32_t& r1, uint32_t& r2, uint32_t& r3, uint32_t a) {
    asm volatile("ldmatrix.sync.aligned.m8n8.x4.trans.shared.b16 {%0,%1,%2,%3}, [%4];\n"
                 : "=r"(r0), "=r"(r1), "=r"(r2), "=r"(r3) : "r"(a));
}

__device__ __forceinline__ void mma16816(float* c, const uint32_t* a, const uint32_t* b) {
    asm volatile(
        "mma.sync.aligned.m16n8k16.row.col.f32.bf16.bf16.f32 "
        "{%0,%1,%2,%3}, {%4,%5,%6,%7}, {%8,%9}, {%0,%1,%2,%3};\n"
        : "+f"(c[0]), "+f"(c[1]), "+f"(c[2]), "+f"(c[3])
        : "r"(a[0]), "r"(a[1]), "r"(a[2]), "r"(a[3]), "r"(b[0]), "r"(b[1]));
}

__device__ __forceinline__ float block_sum_256(float v) {
    __shared__ float red[8];
    #pragma unroll
    for (int o = 16; o; o >>= 1) v += __shfl_xor_sync(0xffffffffu, v, o);
    if ((threadIdx.x & 31) == 0) red[threadIdx.x >> 5] = v;
    __syncthreads();
    float s = 0.f;
    #pragma unroll
    for (int i = 0; i < 8; i++) s += red[i];
    return s;
}

// ---------------- weight fp32 -> bf16 ----------------
__global__ __launch_bounds__(256) void k_convert_w(const float* __restrict__ w) {
    size_t total = (size_t)3 * HIDDEN * HIDDEN / 4;
    const float4* src = (const float4*)w;
    __nv_bfloat162* dst = (__nv_bfloat162*)&g_wb[0][0];
    for (size_t i = (size_t)blockIdx.x * blockDim.x + threadIdx.x; i < total;
         i += (size_t)gridDim.x * blockDim.x) {
        float4 v = src[i];
        dst[2 * i]     = __floats2bfloat162_rn(v.x, v.y);
        dst[2 * i + 1] = __floats2bfloat162_rn(v.z, v.w);
    }
}

// ---------------- stage 0: z = relu(x); resid = z; y = rmsnorm(z)*w0 -> bf16 ----------------
__global__ __launch_bounds__(256) void k_relu_rmsnorm(const float* __restrict__ x,
                                                      const float* __restrict__ nwr) {
    int row = blockIdx.x;
    int t = threadIdx.x;
    size_t base = (size_t)row * HIDDEN;
    const float4* xp = (const float4*)(x + base);
    float4 v0 = xp[2 * t], v1 = xp[2 * t + 1];
    float z[8];
    z[0] = fmaxf(v0.x, 0.f); z[1] = fmaxf(v0.y, 0.f); z[2] = fmaxf(v0.z, 0.f); z[3] = fmaxf(v0.w, 0.f);
    z[4] = fmaxf(v1.x, 0.f); z[5] = fmaxf(v1.y, 0.f); z[6] = fmaxf(v1.z, 0.f); z[7] = fmaxf(v1.w, 0.f);
    float ss = 0.f;
    #pragma unroll
    for (int i = 0; i < 8; i++) ss += z[i] * z[i];
    ss = block_sum_256(ss);
    float rinv = 1.0f / sqrtf(ss * (1.0f / HIDDEN) + 1e-5f);

    float4* rp = (float4*)(g_resid + base);
    rp[2 * t]     = make_float4(z[0], z[1], z[2], z[3]);
    rp[2 * t + 1] = make_float4(z[4], z[5], z[6], z[7]);

    const float4* wp = (const float4*)nwr;
    float4 w0 = wp[2 * t], w1 = wp[2 * t + 1];
    float wv[8] = {w0.x, w0.y, w0.z, w0.w, w1.x, w1.y, w1.z, w1.w};

    union { __nv_bfloat162 h2[4]; uint4 u; } yb;
    #pragma unroll
    for (int i = 0; i < 4; i++)
        yb.h2[i] = __floats2bfloat162_rn(z[2 * i] * rinv * wv[2 * i],
                                         z[2 * i + 1] * rinv * wv[2 * i + 1]);
    ((uint4*)(g_act + base))[t] = yb.u;
}

// ---------------- rmsnorm + group quant (resid already updated by GEMM epilogue) ----------------
__global__ __launch_bounds__(256) void k_rmsnorm_quant(const float* __restrict__ nwr,
                                                       float* __restrict__ out_scale) {
    int row = blockIdx.x;
    int t = threadIdx.x;
    size_t base = (size_t)row * HIDDEN;
    const float4* rp = (const float4*)(g_resid + base);
    float4 r0 = rp[2 * t], r1 = rp[2 * t + 1];
    float z[8] = {r0.x, r0.y, r0.z, r0.w, r1.x, r1.y, r1.z, r1.w};

    float ss = 0.f;
    #pragma unroll
    for (int i = 0; i < 8; i++) ss += z[i] * z[i];
    ss = block_sum_256(ss);
    float rinv = 1.0f / sqrtf(ss * (1.0f / HIDDEN) + 1e-5f);

    const float4* wp = (const float4*)nwr;
    float4 w0 = wp[2 * t], w1 = wp[2 * t + 1];
    float wv[8] = {w0.x, w0.y, w0.z, w0.w, w1.x, w1.y, w1.z, w1.w};

    float y[8];
    float am = 0.f;
    #pragma unroll
    for (int i = 0; i < 8; i++) {
        y[i] = z[i] * rinv * wv[i];
        am = fmaxf(am, fabsf(y[i]));
    }
    // group = 128 elems = 16 consecutive threads
    #pragma unroll
    for (int o = 8; o; o >>= 1) am = fmaxf(am, __shfl_xor_sync(0xffffffffu, am, o));

    float s0 = fmaxf(am, 1e-10f) / 448.0f;
    int e;
    float m = frexpf(s0, &e);
    if (m == 0.5f) e -= 1;
    float scale = ldexpf(1.0f, e);
    if ((t & 15) == 0) out_scale[(size_t)row * NGROUP + (t >> 4)] = scale;

    float inv = 1.0f / scale;
    union { __nv_bfloat162 h2[4]; uint4 u; } yb;
    #pragma unroll
    for (int i = 0; i < 4; i++) {
        __nv_fp8_e4m3 q0 = __nv_fp8_e4m3(y[2 * i] * inv);
        __nv_fp8_e4m3 q1 = __nv_fp8_e4m3(y[2 * i + 1] * inv);
        yb.h2[i] = __floats2bfloat162_rn((float)q0, (float)q1);
    }
    ((uint4*)(g_act + base))[t] = yb.u;
}

// ---------------- final: y4 = rmsnorm(resid)*w3 -> out fp32 (resid updated by GEMM3) ----------------
__global__ __launch_bounds__(256) void k_rmsnorm_out(const float* __restrict__ nwr,
                                                     float* __restrict__ out) {
    int row = blockIdx.x;
    int t = threadIdx.x;
    size_t base = (size_t)row * HIDDEN;
    const float4* rp = (const float4*)(g_resid + base);
    float4 r0 = rp[2 * t], r1 = rp[2 * t + 1];
    float z[8] = {r0.x, r0.y, r0.z, r0.w, r1.x, r1.y, r1.z, r1.w};
    float ss = 0.f;
    #pragma unroll
    for (int i = 0; i < 8; i++) ss += z[i] * z[i];
    ss = block_sum_256(ss);
    float rinv = 1.0f / sqrtf(ss * (1.0f / HIDDEN) + 1e-5f);

    const float4* wp = (const float4*)nwr;
    float4 w0 = wp[2 * t], w1 = wp[2 * t + 1];
    float wv[8] = {w0.x, w0.y, w0.z, w0.w, w1.x, w1.y, w1.z, w1.w};

    float4* op = (float4*)(out + base);
    op[2 * t]     = make_float4(z[0] * rinv * wv[0], z[1] * rinv * wv[1],
                                z[2] * rinv * wv[2], z[3] * rinv * wv[3]);
    op[2 * t + 1] = make_float4(z[4] * rinv * wv[4], z[5] * rinv * wv[5],
                                z[6] * rinv * wv[6], z[7] * rinv * wv[7]);
}

// ---------------- GEMM: g_resid[M,N] += g_act[M,K](bf16) x g_wb[widx][K,N](bf16) ----------------
// Block 128x128x32, 8 warps, warp tile 32x64, 2 CTAs/SM (R6 proven geometry).
// 4-stage cp.async pipeline, prefetch distance 3, one __syncthreads per iteration.
// Epilogue fuses the residual add: resid = acc + resid (in place).
#define ASTR 40
#define BSTR 136
#define NSTAGE 4
#define SZA (128 * ASTR * 2)
#define SZB (32 * BSTR * 2)
#define GEMM_SMEM (NSTAGE * (SZA + SZB))   // 75776 bytes

__global__ __launch_bounds__(256, 2) void k_gemm(int widx) {
    extern __shared__ __align__(16) char smem[];

    const __nv_bfloat16* A = g_act;
    const __nv_bfloat16* B = g_wb[widx];
    float* R = g_resid;

    int tid = threadIdx.x;
    int bn = blockIdx.x, bm = blockIdx.y;
    int lane = tid & 31, warp = tid >> 5;
    int wm = warp & 3;   // 0..3 along M (32 rows each)
    int wn = warp >> 2;  // 0..1 along N (64 cols each)

    // global->shared load mapping (16B per cp.async)
    int a_row = tid >> 2;            // 0..63 (+64)
    int a_col = (tid & 3) * 8;       // halves
    int b_row = tid >> 4;            // 0..15 (+16)
    int b_col = (tid & 15) * 8;      // halves

    const __nv_bfloat16* gA0 = A + (size_t)(bm * 128 + a_row) * HIDDEN + a_col;
    const __nv_bfloat16* gA1 = gA0 + (size_t)64 * HIDDEN;
    const __nv_bfloat16* gB0 = B + (size_t)b_row * HIDDEN + bn * 128 + b_col;
    const __nv_bfloat16* gB1 = gB0 + (size_t)16 * HIDDEN;

    uint32_t sA = (uint32_t)__cvta_generic_to_shared(smem);
    uint32_t sB = sA + NSTAGE * SZA;
    uint32_t sAw = sA + (a_row * ASTR + a_col) * 2;
    uint32_t sBw = sB + (b_row * BSTR + b_col) * 2;

#define LOADSTAGE(s, k0)                                                        \
    {                                                                           \
        cp_async16(sAw + (s) * SZA, gA0 + (k0));                                \
        cp_async16(sAw + (s) * SZA + 64 * ASTR * 2, gA1 + (k0));                \
        cp_async16(sBw + (s) * SZB, gB0 + (size_t)(k0) * HIDDEN);               \
        cp_async16(sBw + (s) * SZB + 16 * BSTR * 2, gB1 + (size_t)(k0) * HIDDEN);\
        asm volatile("cp.async.commit_group;\n" ::: "memory");                  \
    }

    // ldmatrix base addresses (bytes)
    uint32_t aAbase = sA + ((wm * 32 + (lane & 15)) * ASTR + (lane >> 4) * 8) * 2;
    uint32_t aBbase = sB + ((lane & 15) * BSTR + wn * 64 + (lane >> 4) * 8) * 2;

    float acc[2][8][4] = {};

    LOADSTAGE(0, 0);
    LOADSTAGE(1, 32);
    LOADSTAGE(2, 64);

    for (int kt = 0; kt < NKT; kt++) {
        int s = kt & (NSTAGE - 1);
        // stage kt complete once at most 2 newer groups are outstanding
        asm volatile("cp.async.wait_group 2;\n" ::: "memory");
        __syncthreads();   // all warps finished reading stage kt-1

        int jn = kt + 3;
        if (jn < NKT) {
            LOADSTAGE(jn & (NSTAGE - 1), jn * 32);   // overwrites stage kt-1: safe post-barrier
        } else {
            asm volatile("cp.async.commit_group;\n" ::: "memory");  // uniform group accounting
        }

        #pragma unroll
        for (int kk = 0; kk < 32; kk += 16) {
            uint32_t af[2][4];
            uint32_t bf[8][2];
            #pragma unroll
            for (int mt = 0; mt < 2; mt++)
                ldsm_x4(af[mt][0], af[mt][1], af[mt][2], af[mt][3],
                        aAbase + s * SZA + (mt * 16 * ASTR + kk) * 2);
            #pragma unroll
            for (int np = 0; np < 4; np++) {
                uint32_t r0, r1, r2, r3;
                ldsm_x4t(r0, r1, r2, r3,
                         aBbase + s * SZB + (kk * BSTR + np * 16) * 2);
                bf[2 * np][0] = r0; bf[2 * np][1] = r1;
                bf[2 * np + 1][0] = r2; bf[2 * np + 1][1] = r3;
            }
            #pragma unroll
            for (int mt = 0; mt < 2; mt++)
                #pragma unroll
                for (int nt = 0; nt < 8; nt++)
                    mma16816(acc[mt][nt], af[mt], bf[nt]);
        }
    }

    // epilogue: fused residual add, in place (each element owned by one thread)
    int gr = lane >> 2, gc = (lane & 3) * 2;
    #pragma unroll
    for (int mt = 0; mt < 2; mt++) {
        #pragma unroll
        for (int nt = 0; nt < 8; nt++) {
            int r = bm * 128 + wm * 32 + mt * 16 + gr;
            int c = bn * 128 + wn * 64 + nt * 8 + gc;
            float2* p0 = (float2*)&R[(size_t)r * HIDDEN + c];
            float2* p1 = (float2*)&R[(size_t)(r + 8) * HIDDEN + c];
            float2 v0 = *p0, v1 = *p1;
            *p0 = make_float2(acc[mt][nt][0] + v0.x, acc[mt][nt][1] + v0.y);
            *p1 = make_float2(acc[mt][nt][2] + v1.x, acc[mt][nt][3] + v1.y);
        }
    }
#undef LOADSTAGE
}

// ---------------- launch ----------------
extern "C" void kernel_launch(void* const* d_in, const int* in_sizes, int n_in,
                              void* d_out, int out_size) {
    const float* x = (const float*)d_in[0];
    const float* nw = (const float*)d_in[1];
    const float* w = (const float*)d_in[2];
    float* out = (float*)d_out;
    float* y4 = out;
    float* y2s = out + (size_t)TOKENS * HIDDEN;
    float* y3s = y2s + (size_t)TOKENS * NGROUP;
    (void)in_sizes; (void)n_in; (void)out_size;

    static int configured = 0;
    if (!configured) {  // idempotent attribute set (host-side, graph-safe)
        cudaFuncSetAttribute(k_gemm, cudaFuncAttributeMaxDynamicSharedMemorySize, GEMM_SMEM);
        configured = 1;
    }

    dim3 gg(HIDDEN / 128, TOKENS / 128);

    k_convert_w<<<1184, 256>>>(w);
    k_relu_rmsnorm<<<TOKENS, 256>>>(x, nw);
    k_gemm<<<gg, 256, GEMM_SMEM>>>(0);          // resid += y @ w0
    k_rmsnorm_quant<<<TOKENS, 256>>>(nw + HIDDEN, y2s);
    k_gemm<<<gg, 256, GEMM_SMEM>>>(1);          // resid += y2q @ w1
    k_rmsnorm_quant<<<TOKENS, 256>>>(nw + 2 * HIDDEN, y3s);
    k_gemm<<<gg, 256, GEMM_SMEM>>>(2);          // resid += y3q @ w2
    k_rmsnorm_out<<<TOKENS, 256>>>(nw + 3 * HIDDEN, y4);
}

// round 13
// speedup vs baseline: 1.1312x; 1.0189x over previous
#include <cuda_runtime.h>
#include <cuda_bf16.h>
#include <cuda_fp8.h>
#include <cstdint>
#include <math.h>

#define TOKENS 16384
#define HIDDEN 2048
#define NGROUP (HIDDEN / 128)
#define NKT (HIDDEN / 32)     // 64 k-tiles of BK=32

// ---------------- scratch (device globals; no allocation allowed) ----------------
__device__ __nv_bfloat16 g_wb[3][(size_t)HIDDEN * HIDDEN];   // bf16 weights [K,N]
__device__ __nv_bfloat16 g_act[(size_t)TOKENS * HIDDEN];     // bf16 activations (GEMM A)
__device__ float         g_resid[(size_t)TOKENS * HIDDEN];   // fp32 residual
__device__ float         g_gemm[(size_t)TOKENS * HIDDEN];    // fp32 GEMM output

// ---------------- helpers ----------------
__device__ __forceinline__ void cp_async16(uint32_t saddr, const void* gptr) {
    asm volatile("cp.async.cg.shared.global [%0], [%1], 16;\n" :: "r"(saddr), "l"(gptr));
}

__device__ __forceinline__ void ldsm_x4(uint32_t& r0, uint32_t& r1, uint32_t& r2, uint32_t& r3, uint32_t a) {
    asm volatile("ldmatrix.sync.aligned.m8n8.x4.shared.b16 {%0,%1,%2,%3}, [%4];\n"
                 : "=r"(r0), "=r"(r1), "=r"(r2), "=r"(r3) : "r"(a));
}
__device__ __forceinline__ void ldsm_x4t(uint32_t& r0, uint32_t& r1, uint32_t& r2, uint32_t& r3, uint32_t a) {
    asm volatile("ldmatrix.sync.aligned.m8n8.x4.trans.shared.b16 {%0,%1,%2,%3}, [%4];\n"
                 : "=r"(r0), "=r"(r1), "=r"(r2), "=r"(r3) : "r"(a));
}

__device__ __forceinline__ void mma16816(float* c, const uint32_t* a, const uint32_t* b) {
    asm volatile(
        "mma.sync.aligned.m16n8k16.row.col.f32.bf16.bf16.f32 "
        "{%0,%1,%2,%3}, {%4,%5,%6,%7}, {%8,%9}, {%0,%1,%2,%3};\n"
        : "+f"(c[0]), "+f"(c[1]), "+f"(c[2]), "+f"(c[3])
        : "r"(a[0]), "r"(a[1]), "r"(a[2]), "r"(a[3]), "r"(b[0]), "r"(b[1]));
}

__device__ __forceinline__ float block_sum_256(float v) {
    __shared__ float red[8];
    #pragma unroll
    for (int o = 16; o; o >>= 1) v += __shfl_xor_sync(0xffffffffu, v, o);
    if ((threadIdx.x & 31) == 0) red[threadIdx.x >> 5] = v;
    __syncthreads();
    float s = 0.f;
    #pragma unroll
    for (int i = 0; i < 8; i++) s += red[i];
    return s;
}

// ---------------- weight fp32 -> bf16 ----------------
__global__ __launch_bounds__(256) void k_convert_w(const float* __restrict__ w) {
    size_t total = (size_t)3 * HIDDEN * HIDDEN / 4;
    const float4* src = (const float4*)w;
    __nv_bfloat162* dst = (__nv_bfloat162*)&g_wb[0][0];
    for (size_t i = (size_t)blockIdx.x * blockDim.x + threadIdx.x; i < total;
         i += (size_t)gridDim.x * blockDim.x) {
        float4 v = src[i];
        dst[2 * i]     = __floats2bfloat162_rn(v.x, v.y);
        dst[2 * i + 1] = __floats2bfloat162_rn(v.z, v.w);
    }
}

// ---------------- stage 0: z = relu(x); resid = z; y = rmsnorm(z)*w0 -> bf16 ----------------
__global__ __launch_bounds__(256) void k_relu_rmsnorm(const float* __restrict__ x,
                                                      const float* __restrict__ nwr) {
    int row = blockIdx.x;
    int t = threadIdx.x;
    size_t base = (size_t)row * HIDDEN;
    const float4* xp = (const float4*)(x + base);
    float4 v0 = xp[2 * t], v1 = xp[2 * t + 1];
    float z[8];
    z[0] = fmaxf(v0.x, 0.f); z[1] = fmaxf(v0.y, 0.f); z[2] = fmaxf(v0.z, 0.f); z[3] = fmaxf(v0.w, 0.f);
    z[4] = fmaxf(v1.x, 0.f); z[5] = fmaxf(v1.y, 0.f); z[6] = fmaxf(v1.z, 0.f); z[7] = fmaxf(v1.w, 0.f);
    float ss = 0.f;
    #pragma unroll
    for (int i = 0; i < 8; i++) ss += z[i] * z[i];
    ss = block_sum_256(ss);
    float rinv = 1.0f / sqrtf(ss * (1.0f / HIDDEN) + 1e-5f);

    float4* rp = (float4*)(g_resid + base);
    rp[2 * t]     = make_float4(z[0], z[1], z[2], z[3]);
    rp[2 * t + 1] = make_float4(z[4], z[5], z[6], z[7]);

    const float4* wp = (const float4*)nwr;
    float4 w0 = wp[2 * t], w1 = wp[2 * t + 1];
    float wv[8] = {w0.x, w0.y, w0.z, w0.w, w1.x, w1.y, w1.z, w1.w};

    union { __nv_bfloat162 h2[4]; uint4 u; } yb;
    #pragma unroll
    for (int i = 0; i < 4; i++)
        yb.h2[i] = __floats2bfloat162_rn(z[2 * i] * rinv * wv[2 * i],
                                         z[2 * i + 1] * rinv * wv[2 * i + 1]);
    ((uint4*)(g_act + base))[t] = yb.u;
}

// ---------------- fused add + rmsnorm + group quant (ue8m0 / e4m3) ----------------
__global__ __launch_bounds__(256) void k_add_rmsnorm_quant(const float* __restrict__ nwr,
                                                           float* __restrict__ out_scale) {
    int row = blockIdx.x;   // ascending: starts at the GEMM's last-written (L2-hot) rows
    int t = threadIdx.x;
    size_t base = (size_t)row * HIDDEN;
    const float4* gp = (const float4*)(g_gemm + base);
    float4* rp = (float4*)(g_resid + base);
    float4 a0 = gp[2 * t], a1 = gp[2 * t + 1];
    float4 r0 = rp[2 * t], r1 = rp[2 * t + 1];
    float z[8] = {a0.x + r0.x, a0.y + r0.y, a0.z + r0.z, a0.w + r0.w,
                  a1.x + r1.x, a1.y + r1.y, a1.z + r1.z, a1.w + r1.w};
    rp[2 * t]     = make_float4(z[0], z[1], z[2], z[3]);
    rp[2 * t + 1] = make_float4(z[4], z[5], z[6], z[7]);

    float ss = 0.f;
    #pragma unroll
    for (int i = 0; i < 8; i++) ss += z[i] * z[i];
    ss = block_sum_256(ss);
    float rinv = 1.0f / sqrtf(ss * (1.0f / HIDDEN) + 1e-5f);

    const float4* wp = (const float4*)nwr;
    float4 w0 = wp[2 * t], w1 = wp[2 * t + 1];
    float wv[8] = {w0.x, w0.y, w0.z, w0.w, w1.x, w1.y, w1.z, w1.w};

    float y[8];
    float am = 0.f;
    #pragma unroll
    for (int i = 0; i < 8; i++) {
        y[i] = z[i] * rinv * wv[i];
        am = fmaxf(am, fabsf(y[i]));
    }
    // group = 128 elems = 16 consecutive threads
    #pragma unroll
    for (int o = 8; o; o >>= 1) am = fmaxf(am, __shfl_xor_sync(0xffffffffu, am, o));

    float s0 = fmaxf(am, 1e-10f) / 448.0f;
    int e;
    float m = frexpf(s0, &e);
    if (m == 0.5f) e -= 1;
    float scale = ldexpf(1.0f, e);
    if ((t & 15) == 0) out_scale[(size_t)row * NGROUP + (t >> 4)] = scale;

    float inv = 1.0f / scale;
    union { __nv_bfloat162 h2[4]; uint4 u; } yb;
    #pragma unroll
    for (int i = 0; i < 4; i++) {
        __nv_fp8_e4m3 q0 = __nv_fp8_e4m3(y[2 * i] * inv);
        __nv_fp8_e4m3 q1 = __nv_fp8_e4m3(y[2 * i + 1] * inv);
        yb.h2[i] = __floats2bfloat162_rn((float)q0, (float)q1);
    }
    ((uint4*)(g_act + base))[t] = yb.u;
}

// ---------------- final: y4 = rmsnorm(x4 + resid)*w3 -> out fp32 ----------------
__global__ __launch_bounds__(256) void k_add_rmsnorm_out(const float* __restrict__ nwr,
                                                         float* __restrict__ out) {
    int row = blockIdx.x;   // ascending: g_gemm tail (low rows) is hot
    int t = threadIdx.x;
    size_t base = (size_t)row * HIDDEN;
    const float4* gp = (const float4*)(g_gemm + base);
    const float4* rp = (const float4*)(g_resid + base);
    float4 a0 = gp[2 * t], a1 = gp[2 * t + 1];
    float4 r0 = rp[2 * t], r1 = rp[2 * t + 1];
    float z[8] = {a0.x + r0.x, a0.y + r0.y, a0.z + r0.z, a0.w + r0.w,
                  a1.x + r1.x, a1.y + r1.y, a1.z + r1.z, a1.w + r1.w};
    float ss = 0.f;
    #pragma unroll
    for (int i = 0; i < 8; i++) ss += z[i] * z[i];
    ss = block_sum_256(ss);
    float rinv = 1.0f / sqrtf(ss * (1.0f / HIDDEN) + 1e-5f);

    const float4* wp = (const float4*)nwr;
    float4 w0 = wp[2 * t], w1 = wp[2 * t + 1];
    float wv[8] = {w0.x, w0.y, w0.z, w0.w, w1.x, w1.y, w1.z, w1.w};

    float4* op = (float4*)(out + base);
    op[2 * t]     = make_float4(z[0] * rinv * wv[0], z[1] * rinv * wv[1],
                                z[2] * rinv * wv[2], z[3] * rinv * wv[3]);
    op[2 * t + 1] = make_float4(z[4] * rinv * wv[4], z[5] * rinv * wv[5],
                                z[6] * rinv * wv[6], z[7] * rinv * wv[7]);
}

// ---------------- GEMM: g_gemm[M,N] = g_act[M,K](bf16) x g_wb[widx][K,N](bf16), fp32 acc ----------------
// Block 128x128x32, 8 warps, warp tile 32x64, 2 CTAs/SM. 4-stage cp.async pipeline,
// one __syncthreads per iteration, prefetch distance 3 (champion R6 config).
// bm is REVERSED: first-running CTAs (low bid) process HIGH token rows, which the
// preceding elementwise kernel (ascending) wrote last -> L2-hot reads of g_act;
// g_gemm writes then finish at LOW rows -> hot for the next ascending consumer.
#define ASTR 40
#define BSTR 136
#define NSTAGE 4
#define SZA (128 * ASTR * 2)
#define SZB (32 * BSTR * 2)
#define GEMM_SMEM (NSTAGE * (SZA + SZB))   // 75776 bytes

__global__ __launch_bounds__(256, 2) void k_gemm(int widx) {
    extern __shared__ __align__(16) char smem[];

    const __nv_bfloat16* A = g_act;
    const __nv_bfloat16* B = g_wb[widx];
    float* C = g_gemm;

    int tid = threadIdx.x;
    int bn = blockIdx.x;
    int bm = (gridDim.y - 1) - blockIdx.y;   // direction flip for L2 temporal reuse
    int lane = tid & 31, warp = tid >> 5;
    int wm = warp & 3;   // 0..3 along M (32 rows each)
    int wn = warp >> 2;  // 0..1 along N (64 cols each)

    // global->shared load mapping (16B per cp.async)
    int a_row = tid >> 2;            // 0..63 (+64)
    int a_col = (tid & 3) * 8;       // halves
    int b_row = tid >> 4;            // 0..15 (+16)
    int b_col = (tid & 15) * 8;      // halves

    const __nv_bfloat16* gA0 = A + (size_t)(bm * 128 + a_row) * HIDDEN + a_col;
    const __nv_bfloat16* gA1 = gA0 + (size_t)64 * HIDDEN;
    const __nv_bfloat16* gB0 = B + (size_t)b_row * HIDDEN + bn * 128 + b_col;
    const __nv_bfloat16* gB1 = gB0 + (size_t)16 * HIDDEN;

    uint32_t sA = (uint32_t)__cvta_generic_to_shared(smem);
    uint32_t sB = sA + NSTAGE * SZA;
    uint32_t sAw = sA + (a_row * ASTR + a_col) * 2;
    uint32_t sBw = sB + (b_row * BSTR + b_col) * 2;

#define LOADSTAGE(s, k0)                                                        \
    {                                                                           \
        cp_async16(sAw + (s) * SZA, gA0 + (k0));                                \
        cp_async16(sAw + (s) * SZA + 64 * ASTR * 2, gA1 + (k0));                \
        cp_async16(sBw + (s) * SZB, gB0 + (size_t)(k0) * HIDDEN);               \
        cp_async16(sBw + (s) * SZB + 16 * BSTR * 2, gB1 + (size_t)(k0) * HIDDEN);\
        asm volatile("cp.async.commit_group;\n" ::: "memory");                  \
    }

    // ldmatrix base addresses (bytes)
    uint32_t aAbase = sA + ((wm * 32 + (lane & 15)) * ASTR + (lane >> 4) * 8) * 2;
    uint32_t aBbase = sB + ((lane & 15) * BSTR + wn * 64 + (lane >> 4) * 8) * 2;

    float acc[2][8][4] = {};

    LOADSTAGE(0, 0);
    LOADSTAGE(1, 32);
    LOADSTAGE(2, 64);

    for (int kt = 0; kt < NKT; kt++) {
        int s = kt & (NSTAGE - 1);
        // stage kt complete once at most 2 newer groups are outstanding
        asm volatile("cp.async.wait_group 2;\n" ::: "memory");
        __syncthreads();   // all warps finished reading stage kt-1

        int jn = kt + 3;
        if (jn < NKT) {
            LOADSTAGE(jn & (NSTAGE - 1), jn * 32);   // overwrites stage kt-1: safe post-barrier
        } else {
            asm volatile("cp.async.commit_group;\n" ::: "memory");  // uniform group accounting
        }

        #pragma unroll
        for (int kk = 0; kk < 32; kk += 16) {
            uint32_t af[2][4];
            uint32_t bf[8][2];
            #pragma unroll
            for (int mt = 0; mt < 2; mt++)
                ldsm_x4(af[mt][0], af[mt][1], af[mt][2], af[mt][3],
                        aAbase + s * SZA + (mt * 16 * ASTR + kk) * 2);
            #pragma unroll
            for (int np = 0; np < 4; np++) {
                uint32_t r0, r1, r2, r3;
                ldsm_x4t(r0, r1, r2, r3,
                         aBbase + s * SZB + (kk * BSTR + np * 16) * 2);
                bf[2 * np][0] = r0; bf[2 * np][1] = r1;
                bf[2 * np + 1][0] = r2; bf[2 * np + 1][1] = r3;
            }
            #pragma unroll
            for (int mt = 0; mt < 2; mt++)
                #pragma unroll
                for (int nt = 0; nt < 8; nt++)
                    mma16816(acc[mt][nt], af[mt], bf[nt]);
        }
    }

    // epilogue
    int gr = lane >> 2, gc = (lane & 3) * 2;
    #pragma unroll
    for (int mt = 0; mt < 2; mt++) {
        #pragma unroll
        for (int nt = 0; nt < 8; nt++) {
            int r = bm * 128 + wm * 32 + mt * 16 + gr;
            int c = bn * 128 + wn * 64 + nt * 8 + gc;
            *(float2*)&C[(size_t)r * HIDDEN + c] = make_float2(acc[mt][nt][0], acc[mt][nt][1]);
            *(float2*)&C[(size_t)(r + 8) * HIDDEN + c] = make_float2(acc[mt][nt][2], acc[mt][nt][3]);
        }
    }
#undef LOADSTAGE
}

// ---------------- launch ----------------
extern "C" void kernel_launch(void* const* d_in, const int* in_sizes, int n_in,
                              void* d_out, int out_size) {
    const float* x = (const float*)d_in[0];
    const float* nw = (const float*)d_in[1];
    const float* w = (const float*)d_in[2];
    float* out = (float*)d_out;
    float* y4 = out;
    float* y2s = out + (size_t)TOKENS * HIDDEN;
    float* y3s = y2s + (size_t)TOKENS * NGROUP;
    (void)in_sizes; (void)n_in; (void)out_size;

    static int configured = 0;
    if (!configured) {  // idempotent attribute set (host-side, graph-safe)
        cudaFuncSetAttribute(k_gemm, cudaFuncAttributeMaxDynamicSharedMemorySize, GEMM_SMEM);
        configured = 1;
    }

    dim3 gg(HIDDEN / 128, TOKENS / 128);

    k_convert_w<<<1184, 256>>>(w);
    k_relu_rmsnorm<<<TOKENS, 256>>>(x, nw);
    k_gemm<<<gg, 256, GEMM_SMEM>>>(0);
    k_add_rmsnorm_quant<<<TOKENS, 256>>>(nw + HIDDEN, y2s);
    k_gemm<<<gg, 256, GEMM_SMEM>>>(1);
    k_add_rmsnorm_quant<<<TOKENS, 256>>>(nw + 2 * HIDDEN, y3s);
    k_gemm<<<gg, 256, GEMM_SMEM>>>(2);
    k_add_rmsnorm_out<<<TOKENS, 256>>>(nw + 3 * HIDDEN, y4);
}

// round 14
// speedup vs baseline: 1.3318x; 1.1774x over previous
#include <cuda_runtime.h>
#include <cuda_bf16.h>
#include <cuda_fp8.h>
#include <cstdint>
#include <math.h>

#define TOKENS 16384
#define HIDDEN 2048
#define NGROUP (HIDDEN / 128)
#define NKT (HIDDEN / 32)     // 64 k-tiles of BK=32

// ---------------- scratch (device globals; no allocation allowed) ----------------
__device__ __nv_bfloat16 g_wb[3][(size_t)HIDDEN * HIDDEN];   // bf16 weights [K,N]
__device__ __nv_bfloat16 g_act[(size_t)TOKENS * HIDDEN];     // bf16 activations (GEMM A)
__device__ float         g_resid[(size_t)TOKENS * HIDDEN];   // fp32 residual
__device__ float         g_gemm[(size_t)TOKENS * HIDDEN];    // fp32 GEMM output

// ---------------- helpers ----------------
__device__ __forceinline__ void cp_async16(uint32_t saddr, const void* gptr) {
    asm volatile("cp.async.cg.shared.global [%0], [%1], 16;\n" :: "r"(saddr), "l"(gptr));
}

__device__ __forceinline__ void ldsm_x4(uint32_t& r0, uint32_t& r1, uint32_t& r2, uint32_t& r3, uint32_t a) {
    asm volatile("ldmatrix.sync.aligned.m8n8.x4.shared.b16 {%0,%1,%2,%3}, [%4];\n"
                 : "=r"(r0), "=r"(r1), "=r"(r2), "=r"(r3) : "r"(a));
}
__device__ __forceinline__ void ldsm_x4t(uint32_t& r0, uint32_t& r1, uint32_t& r2, uint32_t& r3, uint32_t a) {
    asm volatile("ldmatrix.sync.aligned.m8n8.x4.trans.shared.b16 {%0,%1,%2,%3}, [%4];\n"
                 : "=r"(r0), "=r"(r1), "=r"(r2), "=r"(r3) : "r"(a));
}

__device__ __forceinline__ void mma16816(float* c, const uint32_t* a, const uint32_t* b) {
    asm volatile(
        "mma.sync.aligned.m16n8k16.row.col.f32.bf16.bf16.f32 "
        "{%0,%1,%2,%3}, {%4,%5,%6,%7}, {%8,%9}, {%0,%1,%2,%3};\n"
        : "+f"(c[0]), "+f"(c[1]), "+f"(c[2]), "+f"(c[3])
        : "r"(a[0]), "r"(a[1]), "r"(a[2]), "r"(a[3]), "r"(b[0]), "r"(b[1]));
}

__device__ __forceinline__ float block_sum_256(float v) {
    __shared__ float red[8];
    #pragma unroll
    for (int o = 16; o; o >>= 1) v += __shfl_xor_sync(0xffffffffu, v, o);
    if ((threadIdx.x & 31) == 0) red[threadIdx.x >> 5] = v;
    __syncthreads();
    float s = 0.f;
    #pragma unroll
    for (int i = 0; i < 8; i++) s += red[i];
    return s;
}

// ---------------- weight fp32 -> bf16 ----------------
__global__ __launch_bounds__(256) void k_convert_w(const float* __restrict__ w) {
    size_t total = (size_t)3 * HIDDEN * HIDDEN / 4;
    const float4* src = (const float4*)w;
    __nv_bfloat162* dst = (__nv_bfloat162*)&g_wb[0][0];
    for (size_t i = (size_t)blockIdx.x * blockDim.x + threadIdx.x; i < total;
         i += (size_t)gridDim.x * blockDim.x) {
        float4 v = src[i];
        dst[2 * i]     = __floats2bfloat162_rn(v.x, v.y);
        dst[2 * i + 1] = __floats2bfloat162_rn(v.z, v.w);
    }
}

// ---------------- stage 0: z = relu(x); resid = z; y = rmsnorm(z)*w0 -> bf16 ----------------
__global__ __launch_bounds__(256) void k_relu_rmsnorm(const float* __restrict__ x,
                                                      const float* __restrict__ nwr) {
    int row = blockIdx.x;
    int t = threadIdx.x;
    size_t base = (size_t)row * HIDDEN;
    const float4* xp = (const float4*)(x + base);
    float4 v0 = xp[2 * t], v1 = xp[2 * t + 1];
    float z[8];
    z[0] = fmaxf(v0.x, 0.f); z[1] = fmaxf(v0.y, 0.f); z[2] = fmaxf(v0.z, 0.f); z[3] = fmaxf(v0.w, 0.f);
    z[4] = fmaxf(v1.x, 0.f); z[5] = fmaxf(v1.y, 0.f); z[6] = fmaxf(v1.z, 0.f); z[7] = fmaxf(v1.w, 0.f);
    float ss = 0.f;
    #pragma unroll
    for (int i = 0; i < 8; i++) ss += z[i] * z[i];
    ss = block_sum_256(ss);
    float rinv = 1.0f / sqrtf(ss * (1.0f / HIDDEN) + 1e-5f);

    float4* rp = (float4*)(g_resid + base);
    rp[2 * t]     = make_float4(z[0], z[1], z[2], z[3]);
    rp[2 * t + 1] = make_float4(z[4], z[5], z[6], z[7]);

    const float4* wp = (const float4*)nwr;
    float4 w0 = wp[2 * t], w1 = wp[2 * t + 1];
    float wv[8] = {w0.x, w0.y, w0.z, w0.w, w1.x, w1.y, w1.z, w1.w};

    union { __nv_bfloat162 h2[4]; uint4 u; } yb;
    #pragma unroll
    for (int i = 0; i < 4; i++)
        yb.h2[i] = __floats2bfloat162_rn(z[2 * i] * rinv * wv[2 * i],
                                         z[2 * i + 1] * rinv * wv[2 * i + 1]);
    ((uint4*)(g_act + base))[t] = yb.u;
}

// ---------------- fused add + rmsnorm + group quant (ue8m0 / e4m3) ----------------
__global__ __launch_bounds__(256) void k_add_rmsnorm_quant(const float* __restrict__ nwr,
                                                           float* __restrict__ out_scale) {
    int row = blockIdx.x;   // ascending: starts at the GEMM's last-written (L2-hot) rows
    int t = threadIdx.x;
    size_t base = (size_t)row * HIDDEN;
    const float4* gp = (const float4*)(g_gemm + base);
    float4* rp = (float4*)(g_resid + base);
    float4 a0 = gp[2 * t], a1 = gp[2 * t + 1];
    float4 r0 = rp[2 * t], r1 = rp[2 * t + 1];
    float z[8] = {a0.x + r0.x, a0.y + r0.y, a0.z + r0.z, a0.w + r0.w,
                  a1.x + r1.x, a1.y + r1.y, a1.z + r1.z, a1.w + r1.w};
    rp[2 * t]     = make_float4(z[0], z[1], z[2], z[3]);
    rp[2 * t + 1] = make_float4(z[4], z[5], z[6], z[7]);

    float ss = 0.f;
    #pragma unroll
    for (int i = 0; i < 8; i++) ss += z[i] * z[i];
    ss = block_sum_256(ss);
    float rinv = 1.0f / sqrtf(ss * (1.0f / HIDDEN) + 1e-5f);

    const float4* wp = (const float4*)nwr;
    float4 w0 = wp[2 * t], w1 = wp[2 * t + 1];
    float wv[8] = {w0.x, w0.y, w0.z, w0.w, w1.x, w1.y, w1.z, w1.w};

    float y[8];
    float am = 0.f;
    #pragma unroll
    for (int i = 0; i < 8; i++) {
        y[i] = z[i] * rinv * wv[i];
        am = fmaxf(am, fabsf(y[i]));
    }
    // group = 128 elems = 16 consecutive threads
    #pragma unroll
    for (int o = 8; o; o >>= 1) am = fmaxf(am, __shfl_xor_sync(0xffffffffu, am, o));

    float s0 = fmaxf(am, 1e-10f) / 448.0f;
    int e;
    float m = frexpf(s0, &e);
    if (m == 0.5f) e -= 1;
    float scale = ldexpf(1.0f, e);
    if ((t & 15) == 0) out_scale[(size_t)row * NGROUP + (t >> 4)] = scale;

    float inv = 1.0f / scale;
    union { __nv_bfloat162 h2[4]; uint4 u; } yb;
    #pragma unroll
    for (int i = 0; i < 4; i++) {
        __nv_fp8_e4m3 q0 = __nv_fp8_e4m3(y[2 * i] * inv);
        __nv_fp8_e4m3 q1 = __nv_fp8_e4m3(y[2 * i + 1] * inv);
        yb.h2[i] = __floats2bfloat162_rn((float)q0, (float)q1);
    }
    ((uint4*)(g_act + base))[t] = yb.u;
}

// ---------------- final: y4 = rmsnorm(x4 + resid)*w3 -> out fp32 ----------------
__global__ __launch_bounds__(256) void k_add_rmsnorm_out(const float* __restrict__ nwr,
                                                         float* __restrict__ out) {
    int row = blockIdx.x;   // ascending: g_gemm tail (low rows) is hot
    int t = threadIdx.x;
    size_t base = (size_t)row * HIDDEN;
    const float4* gp = (const float4*)(g_gemm + base);
    const float4* rp = (const float4*)(g_resid + base);
    float4 a0 = gp[2 * t], a1 = gp[2 * t + 1];
    float4 r0 = rp[2 * t], r1 = rp[2 * t + 1];
    float z[8] = {a0.x + r0.x, a0.y + r0.y, a0.z + r0.z, a0.w + r0.w,
                  a1.x + r1.x, a1.y + r1.y, a1.z + r1.z, a1.w + r1.w};
    float ss = 0.f;
    #pragma unroll
    for (int i = 0; i < 8; i++) ss += z[i] * z[i];
    ss = block_sum_256(ss);
    float rinv = 1.0f / sqrtf(ss * (1.0f / HIDDEN) + 1e-5f);

    const float4* wp = (const float4*)nwr;
    float4 w0 = wp[2 * t], w1 = wp[2 * t + 1];
    float wv[8] = {w0.x, w0.y, w0.z, w0.w, w1.x, w1.y, w1.z, w1.w};

    float4* op = (float4*)(out + base);
    op[2 * t]     = make_float4(z[0] * rinv * wv[0], z[1] * rinv * wv[1],
                                z[2] * rinv * wv[2], z[3] * rinv * wv[3]);
    op[2 * t + 1] = make_float4(z[4] * rinv * wv[4], z[5] * rinv * wv[5],
                                z[6] * rinv * wv[6], z[7] * rinv * wv[7]);
}

// ---------------- GEMM: g_gemm[M,N] = g_act[M,K](bf16) x g_wb[widx][K,N](bf16), fp32 acc ----------------
// Block 128x128x32 with FOUR warps (128 threads), warp tile 64x64 (Wm=Wn=2):
// fragment redundancy A=2, B=2 -> smem read traffic 32KB/kt/CTA (was 48KB with 8 warps).
// 32 MMAs per 8 ldmatrix. 2 CTAs/SM (regs ~190x128x2 = 49k <= 64k; smem 75.7KB x2 <= 228KB).
// 4-stage cp.async pipeline, prefetch distance 3, one __syncthreads per iteration.
// bm REVERSED for L2 temporal reuse of producer tails (R13 win).
#define ASTR 40
#define BSTR 136
#define NSTAGE 4
#define SZA (128 * ASTR * 2)
#define SZB (32 * BSTR * 2)
#define GEMM_SMEM (NSTAGE * (SZA + SZB))   // 75776 bytes

__global__ __launch_bounds__(128, 2) void k_gemm(int widx) {
    extern __shared__ __align__(16) char smem[];

    const __nv_bfloat16* A = g_act;
    const __nv_bfloat16* B = g_wb[widx];
    float* C = g_gemm;

    int tid = threadIdx.x;
    int bn = blockIdx.x;
    int bm = (gridDim.y - 1) - blockIdx.y;   // direction flip for L2 temporal reuse
    int lane = tid & 31, warp = tid >> 5;    // warp 0..3
    int wm = warp >> 1;  // 0..1 along M (64 rows each)
    int wn = warp & 1;   // 0..1 along N (64 cols each)

    // global->shared load mapping (16B per cp.async), 4 A-chunks + 4 B-chunks per thread
    int a_row = tid >> 2;            // 0..31 (4 chunks of 32 rows)
    int a_col = (tid & 3) * 8;       // halves
    int b_row = tid >> 4;            // 0..7  (4 chunks of 8 rows)
    int b_col = (tid & 15) * 8;      // halves

    const __nv_bfloat16* gA0 = A + (size_t)(bm * 128 + a_row) * HIDDEN + a_col;
    const __nv_bfloat16* gB0 = B + (size_t)b_row * HIDDEN + bn * 128 + b_col;

    uint32_t sA = (uint32_t)__cvta_generic_to_shared(smem);
    uint32_t sB = sA + NSTAGE * SZA;
    uint32_t sAw = sA + (a_row * ASTR + a_col) * 2;
    uint32_t sBw = sB + (b_row * BSTR + b_col) * 2;

#define LOADSTAGE(s, k0)                                                            \
    {                                                                               \
        cp_async16(sAw + (s) * SZA,                 gA0 + (k0));                    \
        cp_async16(sAw + (s) * SZA + 32 * ASTR * 2, gA0 + (size_t)32 * HIDDEN + (k0)); \
        cp_async16(sAw + (s) * SZA + 64 * ASTR * 2, gA0 + (size_t)64 * HIDDEN + (k0)); \
        cp_async16(sAw + (s) * SZA + 96 * ASTR * 2, gA0 + (size_t)96 * HIDDEN + (k0)); \
        cp_async16(sBw + (s) * SZB,                 gB0 + (size_t)(k0) * HIDDEN);   \
        cp_async16(sBw + (s) * SZB +  8 * BSTR * 2, gB0 + (size_t)((k0) + 8) * HIDDEN); \
        cp_async16(sBw + (s) * SZB + 16 * BSTR * 2, gB0 + (size_t)((k0) + 16) * HIDDEN); \
        cp_async16(sBw + (s) * SZB + 24 * BSTR * 2, gB0 + (size_t)((k0) + 24) * HIDDEN); \
        asm volatile("cp.async.commit_group;\n" ::: "memory");                      \
    }

    // ldmatrix base addresses (bytes)
    uint32_t aAbase = sA + ((wm * 64 + (lane & 15)) * ASTR + (lane >> 4) * 8) * 2;
    uint32_t aBbase = sB + ((lane & 15) * BSTR + wn * 64 + (lane >> 4) * 8) * 2;

    float acc[4][8][4] = {};

    LOADSTAGE(0, 0);
    LOADSTAGE(1, 32);
    LOADSTAGE(2, 64);

    for (int kt = 0; kt < NKT; kt++) {
        int s = kt & (NSTAGE - 1);
        // stage kt complete once at most 2 newer groups are outstanding
        asm volatile("cp.async.wait_group 2;\n" ::: "memory");
        __syncthreads();   // all warps finished reading stage kt-1

        int jn = kt + 3;
        if (jn < NKT) {
            LOADSTAGE(jn & (NSTAGE - 1), jn * 32);   // overwrites stage kt-1: safe post-barrier
        } else {
            asm volatile("cp.async.commit_group;\n" ::: "memory");  // uniform group accounting
        }

        #pragma unroll
        for (int kk = 0; kk < 32; kk += 16) {
            uint32_t af[4][4];
            uint32_t bf[8][2];
            #pragma unroll
            for (int mt = 0; mt < 4; mt++)
                ldsm_x4(af[mt][0], af[mt][1], af[mt][2], af[mt][3],
                        aAbase + s * SZA + (mt * 16 * ASTR + kk) * 2);
            #pragma unroll
            for (int np = 0; np < 4; np++) {
                uint32_t r0, r1, r2, r3;
                ldsm_x4t(r0, r1, r2, r3,
                         aBbase + s * SZB + (kk * BSTR + np * 16) * 2);
                bf[2 * np][0] = r0; bf[2 * np][1] = r1;
                bf[2 * np + 1][0] = r2; bf[2 * np + 1][1] = r3;
            }
            #pragma unroll
            for (int mt = 0; mt < 4; mt++)
                #pragma unroll
                for (int nt = 0; nt < 8; nt++)
                    mma16816(acc[mt][nt], af[mt], bf[nt]);
        }
    }

    // epilogue
    int gr = lane >> 2, gc = (lane & 3) * 2;
    #pragma unroll
    for (int mt = 0; mt < 4; mt++) {
        #pragma unroll
        for (int nt = 0; nt < 8; nt++) {
            int r = bm * 128 + wm * 64 + mt * 16 + gr;
            int c = bn * 128 + wn * 64 + nt * 8 + gc;
            *(float2*)&C[(size_t)r * HIDDEN + c] = make_float2(acc[mt][nt][0], acc[mt][nt][1]);
            *(float2*)&C[(size_t)(r + 8) * HIDDEN + c] = make_float2(acc[mt][nt][2], acc[mt][nt][3]);
        }
    }
#undef LOADSTAGE
}

// ---------------- launch ----------------
extern "C" void kernel_launch(void* const* d_in, const int* in_sizes, int n_in,
                              void* d_out, int out_size) {
    const float* x = (const float*)d_in[0];
    const float* nw = (const float*)d_in[1];
    const float* w = (const float*)d_in[2];
    float* out = (float*)d_out;
    float* y4 = out;
    float* y2s = out + (size_t)TOKENS * HIDDEN;
    float* y3s = y2s + (size_t)TOKENS * NGROUP;
    (void)in_sizes; (void)n_in; (void)out_size;

    static int configured = 0;
    if (!configured) {  // idempotent attribute set (host-side, graph-safe)
        cudaFuncSetAttribute(k_gemm, cudaFuncAttributeMaxDynamicSharedMemorySize, GEMM_SMEM);
        configured = 1;
    }

    dim3 gg(HIDDEN / 128, TOKENS / 128);

    k_convert_w<<<1184, 256>>>(w);
    k_relu_rmsnorm<<<TOKENS, 256>>>(x, nw);
    k_gemm<<<gg, 128, GEMM_SMEM>>>(0);
    k_add_rmsnorm_quant<<<TOKENS, 256>>>(nw + HIDDEN, y2s);
    k_gemm<<<gg, 128, GEMM_SMEM>>>(1);
    k_add_rmsnorm_quant<<<TOKENS, 256>>>(nw + 2 * HIDDEN, y3s);
    k_gemm<<<gg, 128, GEMM_SMEM>>>(2);
    k_add_rmsnorm_out<<<TOKENS, 256>>>(nw + 3 * HIDDEN, y4);
}